// round 7
// baseline (speedup 1.0000x reference)
#include <cuda_runtime.h>
#include <cuda_bf16.h>
#include <cstdint>

// Problem constants (fixed by the dataset)
#define NN   20000
#define EE   320000
#define DIN  512
#define DH   256
#define GG   128
#define K1P  (3*DIN)   // 1536
#define K2P  (3*DH)    // 768

// ---------------- device scratch (static allocation only) ----------------
__device__ int            g_deg[NN];
__device__ int            g_cursor[NN];
__device__ int            g_rowptr[NN + 1];
__device__ float          g_dinv[NN];
__device__ int            g_csr[EE + NN];
__device__ __nv_bfloat16  g_A1[(size_t)NN * K1P];    // [hi | lo | hi] of x
__device__ __nv_bfloat16  g_A2[(size_t)NN * K2P];    // [hi | lo | hi] of h1 (written by agg1)
__device__ __nv_bfloat16  g_W1p[(size_t)K1P * DH];   // [W1_hi ; W1_hi ; W1_lo]
__device__ __nv_bfloat16  g_W2p[(size_t)K2P * DH];
__device__ float          g_XW[(size_t)NN * DH];     // GEMM output (reused both layers)
__device__ float          g_H2[(size_t)NN * DH];     // layer-2 node features

// ---------------- graph preprocessing ----------------
__global__ void k_init() {
    int i = blockIdx.x * blockDim.x + threadIdx.x;
    if (i < NN) { g_deg[i] = 1; g_cursor[i] = 0; }   // deg starts at 1 (self loop)
}

__global__ void k_count(const int* __restrict__ dst) {
    int e = blockIdx.x * blockDim.x + threadIdx.x;
    if (e < EE) atomicAdd(&g_deg[dst[e]], 1);
}

// single-block exclusive scan of g_deg -> g_rowptr, plus dinv = rsqrt(deg)
__global__ void k_scan() {
    __shared__ int partial[1024];
    const int tid = threadIdx.x;
    const int C = (NN + 1023) / 1024;   // 20
    int base = tid * C;
    int s = 0;
    for (int j = 0; j < C; j++) if (base + j < NN) s += g_deg[base + j];
    partial[tid] = s;
    __syncthreads();
    for (int off = 1; off < 1024; off <<= 1) {
        int v = (tid >= off) ? partial[tid - off] : 0;
        __syncthreads();
        partial[tid] += v;
        __syncthreads();
    }
    int run = partial[tid] - s;   // exclusive prefix for this chunk
    for (int j = 0; j < C; j++) {
        if (base + j < NN) {
            int d = g_deg[base + j];
            g_rowptr[base + j] = run;
            g_dinv[base + j] = rsqrtf((float)d);
            run += d;
        }
    }
    if (tid == 1023) g_rowptr[NN] = run;
}

__global__ void k_fill(const int* __restrict__ src, const int* __restrict__ dst) {
    int idx = blockIdx.x * blockDim.x + threadIdx.x;
    if (idx < EE) {
        int d = dst[idx];
        int pos = g_rowptr[d] + atomicAdd(&g_cursor[d], 1);
        g_csr[pos] = src[idx];
    } else if (idx < EE + NN) {
        int i = idx - EE;   // self loop
        int pos = g_rowptr[i] + atomicAdd(&g_cursor[i], 1);
        g_csr[pos] = i;
    }
}

// ---------------- bf16 hi/lo split conversions ----------------
__global__ void k_convx(const float* __restrict__ x) {
    int idx = blockIdx.x * blockDim.x + threadIdx.x;
    if (idx >= NN * DIN) return;
    int i = idx >> 9;          // /512
    int k = idx & (DIN - 1);
    float v = x[idx];
    __nv_bfloat16 hi = __float2bfloat16(v);
    __nv_bfloat16 lo = __float2bfloat16(v - __bfloat162float(hi));
    size_t base = (size_t)i * K1P;
    g_A1[base + k]             = hi;
    g_A1[base + DIN + k]       = lo;
    g_A1[base + 2 * DIN + k]   = hi;
}

__global__ void k_wprep(const float* __restrict__ W, int layer) {
    const int K = (layer == 0) ? DIN : DH;
    __nv_bfloat16* Wp = (layer == 0) ? g_W1p : g_W2p;
    int idx = blockIdx.x * blockDim.x + threadIdx.x;
    if (idx >= K * DH) return;
    float v = W[idx];
    __nv_bfloat16 hi = __float2bfloat16(v);
    __nv_bfloat16 lo = __float2bfloat16(v - __bfloat162float(hi));
    Wp[idx]                = hi;   // rows [0,K)   : W_hi
    Wp[(size_t)K * DH + idx]       = hi;   // rows [K,2K)  : W_hi (pairs with A_lo)
    Wp[(size_t)2 * K * DH + idx]   = lo;   // rows [2K,3K) : W_lo (pairs with A_hi)
}

// ---------------- bf16 GEMM: C[M,256] = A'[M,K'] @ W'[K',256] ----------------
#define BM 128
#define BN 128
#define BK 32
#define AP (BK + 8)    // 40 bf16 row stride (conflict-free ldmatrix)
#define BP (BN + 8)    // 136

#define MMA16816(d, a, b0_, b1_)                                                  \
    asm volatile("mma.sync.aligned.m16n8k16.row.col.f32.bf16.bf16.f32 "           \
                 "{%0,%1,%2,%3}, {%4,%5,%6,%7}, {%8,%9}, {%0,%1,%2,%3};"          \
                 : "+f"((d)[0]), "+f"((d)[1]), "+f"((d)[2]), "+f"((d)[3])          \
                 : "r"((a)[0]), "r"((a)[1]), "r"((a)[2]), "r"((a)[3]),             \
                   "r"(b0_), "r"(b1_))

__global__ __launch_bounds__(256, 2) void k_gemm(int layer, int M) {
    const __nv_bfloat16* __restrict__ A = (layer == 0) ? g_A1 : g_A2;
    const __nv_bfloat16* __restrict__ B = (layer == 0) ? g_W1p : g_W2p;
    float* __restrict__ C = g_XW;
    const int K = (layer == 0) ? K1P : K2P;

    __shared__ __align__(16) __nv_bfloat16 As[2][BM][AP];
    __shared__ __align__(16) __nv_bfloat16 Bs[2][BK][BP];

    const int tid  = threadIdx.x;
    const int lane = tid & 31;
    const int wid  = tid >> 5;
    const int wm   = wid & 3;    // 4 warps along M, 32 rows each
    const int wn   = wid >> 2;   // 2 warps along N, 64 cols each
    const int bm   = blockIdx.x * BM;
    const int bn   = blockIdx.y * BN;

    float c[2][8][4];
#pragma unroll
    for (int mt = 0; mt < 2; mt++)
#pragma unroll
        for (int nt = 0; nt < 8; nt++)
#pragma unroll
            for (int r = 0; r < 4; r++) c[mt][nt][r] = 0.f;

    auto load_stage = [&](int buf, int k0) {
#pragma unroll
        for (int j = 0; j < 2; j++) {
            int ch = tid + j * 256;
            // A chunk: 512 x 16B
            int ar = ch >> 2, ac = (ch & 3) * 8;
            const __nv_bfloat16* asrc = A + (size_t)(bm + ar) * K + k0 + ac;
            uint32_t adst = (uint32_t)__cvta_generic_to_shared(&As[buf][ar][ac]);
            int asz = (bm + ar < M) ? 16 : 0;
            asm volatile("cp.async.cg.shared.global [%0], [%1], 16, %2;\n"
                         :: "r"(adst), "l"(asrc), "r"(asz));
            // B chunk: 512 x 16B
            int br = ch >> 4, bc = (ch & 15) * 8;
            const __nv_bfloat16* bsrc = B + (size_t)(k0 + br) * DH + bn + bc;
            uint32_t bdst = (uint32_t)__cvta_generic_to_shared(&Bs[buf][br][bc]);
            asm volatile("cp.async.cg.shared.global [%0], [%1], 16, %2;\n"
                         :: "r"(bdst), "l"(bsrc), "r"(16));
        }
        asm volatile("cp.async.commit_group;\n");
    };

    const int KT = K / BK;
    load_stage(0, 0);

    for (int kt = 0; kt < KT; ++kt) {
        asm volatile("cp.async.wait_group 0;\n");
        __syncthreads();
        if (kt + 1 < KT) load_stage((kt + 1) & 1, (kt + 1) * BK);
        const int buf = kt & 1;

#pragma unroll
        for (int kk = 0; kk < BK; kk += 16) {
            uint32_t a[2][4];
#pragma unroll
            for (int mt = 0; mt < 2; mt++) {
                const __nv_bfloat16* p =
                    &As[buf][wm * 32 + mt * 16 + (lane & 15)][kk + (lane >> 4) * 8];
                uint32_t sp = (uint32_t)__cvta_generic_to_shared(p);
                asm volatile("ldmatrix.sync.aligned.m8n8.x4.shared.b16 {%0,%1,%2,%3}, [%4];"
                             : "=r"(a[mt][0]), "=r"(a[mt][1]), "=r"(a[mt][2]), "=r"(a[mt][3])
                             : "r"(sp));
            }
#pragma unroll
            for (int ng = 0; ng < 4; ++ng) {
                uint32_t bb[4];
                const __nv_bfloat16* p =
                    &Bs[buf][kk + (lane & 15)][wn * 64 + ng * 16 + (lane >> 4) * 8];
                uint32_t sp = (uint32_t)__cvta_generic_to_shared(p);
                asm volatile("ldmatrix.sync.aligned.m8n8.x4.trans.shared.b16 {%0,%1,%2,%3}, [%4];"
                             : "=r"(bb[0]), "=r"(bb[1]), "=r"(bb[2]), "=r"(bb[3])
                             : "r"(sp));
#pragma unroll
                for (int mt = 0; mt < 2; mt++) {
                    MMA16816(c[mt][2 * ng],     a[mt], bb[0], bb[1]);
                    MMA16816(c[mt][2 * ng + 1], a[mt], bb[2], bb[3]);
                }
            }
        }
    }

    // epilogue
#pragma unroll
    for (int mt = 0; mt < 2; mt++) {
        int r0 = bm + wm * 32 + mt * 16 + (lane >> 2);
#pragma unroll
        for (int nt = 0; nt < 8; nt++) {
            int col = bn + wn * 64 + nt * 8 + (lane & 3) * 2;
            if (r0 < M)
                *(float2*)&C[(size_t)r0 * DH + col] = make_float2(c[mt][nt][0], c[mt][nt][1]);
            if (r0 + 8 < M)
                *(float2*)&C[(size_t)(r0 + 8) * DH + col] = make_float2(c[mt][nt][2], c[mt][nt][3]);
        }
    }
}

// ---------------- aggregation: out[d] = relu(dinv[d]*sum_{s in N(d)} dinv[s]*XW[s] + b) --------
// mode 0: emit bf16 hi/lo/hi split into g_A2 (feeds GEMM2).  mode 1: emit f32 into g_H2.
__global__ __launch_bounds__(256) void k_agg(const float* __restrict__ bias, int mode) {
    int g = blockIdx.x * 4 + (threadIdx.x >> 6);   // dst node
    int t = threadIdx.x & 63;                      // owns features [4t, 4t+4)
    if (g >= NN) return;
    const int beg = g_rowptr[g], end = g_rowptr[g + 1];
    float ax = 0.f, ay = 0.f, az = 0.f, aw = 0.f;
    const float* __restrict__ xw = g_XW;
    int e = beg;
    for (; e + 1 < end; e += 2) {
        int s0 = g_csr[e], s1 = g_csr[e + 1];
        float c0 = g_dinv[s0], c1 = g_dinv[s1];
        float4 v0 = *(const float4*)(xw + (size_t)s0 * DH + t * 4);
        float4 v1 = *(const float4*)(xw + (size_t)s1 * DH + t * 4);
        ax += c0 * v0.x + c1 * v1.x;
        ay += c0 * v0.y + c1 * v1.y;
        az += c0 * v0.z + c1 * v1.z;
        aw += c0 * v0.w + c1 * v1.w;
    }
    if (e < end) {
        int s0 = g_csr[e];
        float c0 = g_dinv[s0];
        float4 v0 = *(const float4*)(xw + (size_t)s0 * DH + t * 4);
        ax += c0 * v0.x; ay += c0 * v0.y; az += c0 * v0.z; aw += c0 * v0.w;
    }
    float dd = g_dinv[g];
    float4 b = *(const float4*)(bias + t * 4);
    float rx = fmaxf(dd * ax + b.x, 0.f);
    float ry = fmaxf(dd * ay + b.y, 0.f);
    float rz = fmaxf(dd * az + b.z, 0.f);
    float rw = fmaxf(dd * aw + b.w, 0.f);

    if (mode == 0) {
        __nv_bfloat16 hx = __float2bfloat16(rx), hy = __float2bfloat16(ry);
        __nv_bfloat16 hz = __float2bfloat16(rz), hw = __float2bfloat16(rw);
        __nv_bfloat16 lx = __float2bfloat16(rx - __bfloat162float(hx));
        __nv_bfloat16 ly = __float2bfloat16(ry - __bfloat162float(hy));
        __nv_bfloat16 lz = __float2bfloat16(rz - __bfloat162float(hz));
        __nv_bfloat16 lw = __float2bfloat16(rw - __bfloat162float(hw));
        __nv_bfloat16* dst = g_A2 + (size_t)g * K2P + t * 4;
        *(__nv_bfloat162*)(dst)           = __halves2bfloat162(hx, hy);
        *(__nv_bfloat162*)(dst + 2)       = __halves2bfloat162(hz, hw);
        *(__nv_bfloat162*)(dst + DH)      = __halves2bfloat162(lx, ly);
        *(__nv_bfloat162*)(dst + DH + 2)  = __halves2bfloat162(lz, lw);
        *(__nv_bfloat162*)(dst + 2 * DH)      = __halves2bfloat162(hx, hy);
        *(__nv_bfloat162*)(dst + 2 * DH + 2)  = __halves2bfloat162(hz, hw);
    } else {
        *(float4*)(g_H2 + (size_t)g * DH + t * 4) = make_float4(rx, ry, rz, rw);
    }
}

// ---------------- pooling + fc head: out[g] = mean_{batch==g}(h2) @ w_fc + b_fc --------------
__global__ __launch_bounds__(256) void k_pool(const int* __restrict__ batch,
                                              const float* __restrict__ wfc,
                                              const float* __restrict__ bfc,
                                              float* __restrict__ out) {
    const int g = blockIdx.x;
    __shared__ int s_lo, s_hi;
    __shared__ float red[256];
    if (threadIdx.x == 0) {
        int lo = 0, hi = NN;
        while (lo < hi) { int m = (lo + hi) >> 1; if (batch[m] < g) lo = m + 1; else hi = m; }
        s_lo = lo;
        hi = NN;
        while (lo < hi) { int m = (lo + hi) >> 1; if (batch[m] < g + 1) lo = m + 1; else hi = m; }
        s_hi = lo;
    }
    __syncthreads();
    const int lo = s_lo, hi = s_hi;
    const int f = threadIdx.x;
    float acc = 0.f;
    for (int r = lo; r < hi; r++) acc += g_H2[(size_t)r * DH + f];
    float cnt = (float)((hi - lo) > 1 ? (hi - lo) : 1);
    red[f] = (acc / cnt) * wfc[f];
    __syncthreads();
    for (int off = 128; off > 0; off >>= 1) {
        if (f < off) red[f] += red[f + off];
        __syncthreads();
    }
    if (f == 0) out[g] = red[0] + bfc[0];
}

// ---------------- launch ----------------
extern "C" void kernel_launch(void* const* d_in, const int* in_sizes, int n_in,
                              void* d_out, int out_size) {
    const float* x    = (const float*)d_in[0];
    const int*   ei   = (const int*)d_in[1];   // [2, E]: row0 = src, row1 = dst
    const int*   bat  = (const int*)d_in[2];
    const float* W1   = (const float*)d_in[3];
    const float* b1   = (const float*)d_in[4];
    const float* W2   = (const float*)d_in[5];
    const float* b2   = (const float*)d_in[6];
    const float* wfc  = (const float*)d_in[7];
    const float* bfc  = (const float*)d_in[8];
    float* out = (float*)d_out;
    const int* src = ei;
    const int* dst = ei + EE;

    // graph structure (CSR by dst, with self loops)
    k_init<<<(NN + 255) / 256, 256>>>();
    k_count<<<(EE + 255) / 256, 256>>>(dst);
    k_scan<<<1, 1024>>>();
    k_fill<<<(EE + NN + 255) / 256, 256>>>(src, dst);

    // bf16 split operands
    k_convx<<<(NN * DIN + 255) / 256, 256>>>(x);
    k_wprep<<<(DIN * DH + 255) / 256, 256>>>(W1, 0);
    k_wprep<<<(DH * DH + 255) / 256, 256>>>(W2, 1);

    dim3 gg((NN + BM - 1) / BM, DH / BN);   // 157 x 2

    // layer 1: XW = x @ W1 (split), then aggregate + bias + relu -> bf16 split h1
    k_gemm<<<gg, 256>>>(0, NN);
    k_agg<<<NN / 4, 256>>>(b1, 0);

    // layer 2: XW = h1 @ W2 (split), then aggregate + bias + relu -> f32 h2
    k_gemm<<<gg, 256>>>(1, NN);
    k_agg<<<NN / 4, 256>>>(b2, 1);

    // pooling + head
    k_pool<<<GG, 256>>>(bat, wfc, bfc, out);
}

// round 12
// speedup vs baseline: 1.2877x; 1.2877x over previous
#include <cuda_runtime.h>
#include <cuda_bf16.h>
#include <cstdint>

// Problem constants (fixed by the dataset)
#define NN   20000
#define EE   320000
#define DIN  512
#define DH   256
#define GG   128
#define K1P  (3*DIN)   // 1536 logical K for layer-1 split GEMM
#define K2P  (3*DH)    // 768

// ---------------- device scratch (static allocation only) ----------------
__device__ int            g_deg[NN];
__device__ int            g_cursor[NN];
__device__ int            g_rowptr[NN + 1];
__device__ float          g_dinv[NN];
__device__ int            g_csr[EE + NN];
__device__ __nv_bfloat16  g_A1[(size_t)NN * (2 * DIN)];   // [hi | lo] of x
__device__ __nv_bfloat16  g_A2[(size_t)NN * (2 * DH)];    // [hi | lo] of h1 (written by agg1)
__device__ __nv_bfloat16  g_W1p[(size_t)K1P * DH];        // [W1_hi ; W1_hi ; W1_lo]  (K-major)
__device__ __nv_bfloat16  g_W2p[(size_t)K2P * DH];
__device__ float          g_XW[(size_t)NN * DH];          // GEMM output (reused both layers)
__device__ float          g_H2[(size_t)NN * DH];          // layer-2 node features

// ---------------- graph preprocessing ----------------
__global__ void k_init() {
    int i = blockIdx.x * blockDim.x + threadIdx.x;
    if (i < NN) { g_deg[i] = 1; g_cursor[i] = 0; }   // deg starts at 1 (self loop)
}

__global__ void k_count(const int* __restrict__ dst) {
    int e = blockIdx.x * blockDim.x + threadIdx.x;
    if (e < EE) atomicAdd(&g_deg[dst[e]], 1);
}

// single-block exclusive scan of g_deg -> g_rowptr, plus dinv = rsqrt(deg)
__global__ void k_scan() {
    __shared__ int partial[1024];
    const int tid = threadIdx.x;
    const int C = (NN + 1023) / 1024;   // 20
    int base = tid * C;
    int s = 0;
    for (int j = 0; j < C; j++) if (base + j < NN) s += g_deg[base + j];
    partial[tid] = s;
    __syncthreads();
    for (int off = 1; off < 1024; off <<= 1) {
        int v = (tid >= off) ? partial[tid - off] : 0;
        __syncthreads();
        partial[tid] += v;
        __syncthreads();
    }
    int run = partial[tid] - s;   // exclusive prefix for this chunk
    for (int j = 0; j < C; j++) {
        if (base + j < NN) {
            int d = g_deg[base + j];
            g_rowptr[base + j] = run;
            g_dinv[base + j] = rsqrtf((float)d);
            run += d;
        }
    }
    if (tid == 1023) g_rowptr[NN] = run;
}

__global__ void k_fill(const int* __restrict__ src, const int* __restrict__ dst) {
    int idx = blockIdx.x * blockDim.x + threadIdx.x;
    if (idx < EE) {
        int d = dst[idx];
        int pos = g_rowptr[d] + atomicAdd(&g_cursor[d], 1);
        g_csr[pos] = src[idx];
    } else if (idx < EE + NN) {
        int i = idx - EE;   // self loop
        int pos = g_rowptr[i] + atomicAdd(&g_cursor[i], 1);
        g_csr[pos] = i;
    }
}

// ---------------- bf16 hi/lo split conversions ----------------
__global__ void k_convx(const float* __restrict__ x) {
    int idx4 = blockIdx.x * blockDim.x + threadIdx.x;   // over NN*DIN/4
    if (idx4 >= NN * DIN / 4) return;
    int i = idx4 / (DIN / 4);
    int k = (idx4 % (DIN / 4)) * 4;
    float4 v = ((const float4*)x)[idx4];
    __nv_bfloat16 hx = __float2bfloat16(v.x), hy = __float2bfloat16(v.y);
    __nv_bfloat16 hz = __float2bfloat16(v.z), hw = __float2bfloat16(v.w);
    __nv_bfloat16 lx = __float2bfloat16(v.x - __bfloat162float(hx));
    __nv_bfloat16 ly = __float2bfloat16(v.y - __bfloat162float(hy));
    __nv_bfloat16 lz = __float2bfloat16(v.z - __bfloat162float(hz));
    __nv_bfloat16 lw = __float2bfloat16(v.w - __bfloat162float(hw));
    __nv_bfloat16* base = g_A1 + (size_t)i * (2 * DIN);
    *(__nv_bfloat162*)(base + k)           = __halves2bfloat162(hx, hy);
    *(__nv_bfloat162*)(base + k + 2)       = __halves2bfloat162(hz, hw);
    *(__nv_bfloat162*)(base + DIN + k)     = __halves2bfloat162(lx, ly);
    *(__nv_bfloat162*)(base + DIN + k + 2) = __halves2bfloat162(lz, lw);
}

// W' K-major: rows [0,K)=W_hi, [K,2K)=W_hi, [2K,3K)=W_lo   (pairs with A hi,lo,hi)
__global__ void k_wprep(const float* __restrict__ W, int layer) {
    const int K = (layer == 0) ? DIN : DH;
    __nv_bfloat16* Wp = (layer == 0) ? g_W1p : g_W2p;
    int idx = blockIdx.x * blockDim.x + threadIdx.x;
    if (idx >= K * DH) return;
    float v = W[idx];
    __nv_bfloat16 hi = __float2bfloat16(v);
    __nv_bfloat16 lo = __float2bfloat16(v - __bfloat162float(hi));
    Wp[idx]                      = hi;   // rows [0,K)   : W_hi
    Wp[(size_t)K * DH + idx]     = hi;   // rows [K,2K)  : W_hi (pairs with A_lo)
    Wp[(size_t)2 * K * DH + idx] = lo;   // rows [2K,3K) : W_lo (pairs with A_hi)
}

// ---------------- bf16 GEMM: C[M,256] = A'[M,K'] @ W'[K',256] ----------------
// A physically [hi|lo] (2*Kb); logical K' = 3*Kb remapped per stage (hi,lo,hi).
#define BM 128
#define BN 128
#define BK 32
#define AP (BK + 8)    // 40 bf16 row stride (conflict-free ldmatrix)
#define BP (BN + 8)    // 136

#define MMA16816(d, a, b0_, b1_)                                                  \
    asm volatile("mma.sync.aligned.m16n8k16.row.col.f32.bf16.bf16.f32 "           \
                 "{%0,%1,%2,%3}, {%4,%5,%6,%7}, {%8,%9}, {%0,%1,%2,%3};"          \
                 : "+f"((d)[0]), "+f"((d)[1]), "+f"((d)[2]), "+f"((d)[3])          \
                 : "r"((a)[0]), "r"((a)[1]), "r"((a)[2]), "r"((a)[3]),             \
                   "r"(b0_), "r"(b1_))

__global__ __launch_bounds__(256, 2) void k_gemm(int layer, int M) {
    const __nv_bfloat16* __restrict__ A = (layer == 0) ? g_A1 : g_A2;
    const __nv_bfloat16* __restrict__ B = (layer == 0) ? g_W1p : g_W2p;
    float* __restrict__ C = g_XW;
    const int Kb = (layer == 0) ? DIN : DH;

    __shared__ __align__(16) __nv_bfloat16 As[2][BM][AP];
    __shared__ __align__(16) __nv_bfloat16 Bs[2][BK][BP];

    const int tid  = threadIdx.x;
    const int lane = tid & 31;
    const int wid  = tid >> 5;
    const int wm   = wid & 3;    // 4 warps along M, 32 rows each
    const int wn   = wid >> 2;   // 2 warps along N, 64 cols each
    const int bm   = blockIdx.x * BM;
    const int bn   = blockIdx.y * BN;

    float c[2][8][4];
#pragma unroll
    for (int mt = 0; mt < 2; mt++)
#pragma unroll
        for (int nt = 0; nt < 8; nt++)
#pragma unroll
            for (int r = 0; r < 4; r++) c[mt][nt][r] = 0.f;

    auto load_stage = [&](int buf, int kt) {
        const int k0  = kt * BK;              // logical K' offset
        const int seg = k0 / Kb;              // 0,1,2 -> A: hi,lo,hi
        const int ka  = ((seg == 2) ? 0 : seg) * Kb + (k0 - seg * Kb);
#pragma unroll
        for (int j = 0; j < 2; j++) {
            int ch = tid + j * 256;
            // A chunk: 512 x 16B  (rows of the physical [hi|lo] buffer)
            int ar = ch >> 2, ac = (ch & 3) * 8;
            const __nv_bfloat16* asrc = A + (size_t)(bm + ar) * (2 * Kb) + ka + ac;
            uint32_t adst = (uint32_t)__cvta_generic_to_shared(&As[buf][ar][ac]);
            int asz = (bm + ar < M) ? 16 : 0;
            asm volatile("cp.async.cg.shared.global [%0], [%1], 16, %2;\n"
                         :: "r"(adst), "l"(asrc), "r"(asz));
            // B chunk: 512 x 16B (B stays logical [3*Kb][256])
            int br = ch >> 4, bc = (ch & 15) * 8;
            const __nv_bfloat16* bsrc = B + (size_t)(k0 + br) * DH + bn + bc;
            uint32_t bdst = (uint32_t)__cvta_generic_to_shared(&Bs[buf][br][bc]);
            asm volatile("cp.async.cg.shared.global [%0], [%1], 16, %2;\n"
                         :: "r"(bdst), "l"(bsrc), "r"(16));
        }
        asm volatile("cp.async.commit_group;\n");
    };

    const int KT = 3 * Kb / BK;
    load_stage(0, 0);

    for (int kt = 0; kt < KT; ++kt) {
        asm volatile("cp.async.wait_group 0;\n");
        __syncthreads();
        if (kt + 1 < KT) load_stage((kt + 1) & 1, kt + 1);
        const int buf = kt & 1;

#pragma unroll
        for (int kk = 0; kk < BK; kk += 16) {
            uint32_t a[2][4];
#pragma unroll
            for (int mt = 0; mt < 2; mt++) {
                const __nv_bfloat16* p =
                    &As[buf][wm * 32 + mt * 16 + (lane & 15)][kk + (lane >> 4) * 8];
                uint32_t sp = (uint32_t)__cvta_generic_to_shared(p);
                asm volatile("ldmatrix.sync.aligned.m8n8.x4.shared.b16 {%0,%1,%2,%3}, [%4];"
                             : "=r"(a[mt][0]), "=r"(a[mt][1]), "=r"(a[mt][2]), "=r"(a[mt][3])
                             : "r"(sp));
            }
#pragma unroll
            for (int ng = 0; ng < 4; ++ng) {
                uint32_t bb[4];
                const __nv_bfloat16* p =
                    &Bs[buf][kk + (lane & 15)][wn * 64 + ng * 16 + (lane >> 4) * 8];
                uint32_t sp = (uint32_t)__cvta_generic_to_shared(p);
                asm volatile("ldmatrix.sync.aligned.m8n8.x4.trans.shared.b16 {%0,%1,%2,%3}, [%4];"
                             : "=r"(bb[0]), "=r"(bb[1]), "=r"(bb[2]), "=r"(bb[3])
                             : "r"(sp));
#pragma unroll
                for (int mt = 0; mt < 2; mt++) {
                    MMA16816(c[mt][2 * ng],     a[mt], bb[0], bb[1]);
                    MMA16816(c[mt][2 * ng + 1], a[mt], bb[2], bb[3]);
                }
            }
        }
    }

    // epilogue
#pragma unroll
    for (int mt = 0; mt < 2; mt++) {
        int r0 = bm + wm * 32 + mt * 16 + (lane >> 2);
#pragma unroll
        for (int nt = 0; nt < 8; nt++) {
            int col = bn + wn * 64 + nt * 8 + (lane & 3) * 2;
            if (r0 < M)
                *(float2*)&C[(size_t)r0 * DH + col] = make_float2(c[mt][nt][0], c[mt][nt][1]);
            if (r0 + 8 < M)
                *(float2*)&C[(size_t)(r0 + 8) * DH + col] = make_float2(c[mt][nt][2], c[mt][nt][3]);
        }
    }
}

// ---------------- aggregation: out[d] = relu(dinv[d]*sum_{s in N(d)} dinv[s]*XW[s] + b) --------
// mode 0: emit bf16 [hi|lo] into g_A2 (feeds GEMM2).  mode 1: emit f32 into g_H2.
__global__ __launch_bounds__(256) void k_agg(const float* __restrict__ bias, int mode) {
    int g = blockIdx.x * 4 + (threadIdx.x >> 6);   // dst node
    int t = threadIdx.x & 63;                      // owns features [4t, 4t+4)
    if (g >= NN) return;
    const int beg = g_rowptr[g], end = g_rowptr[g + 1];
    float ax = 0.f, ay = 0.f, az = 0.f, aw = 0.f;
    const float* __restrict__ xw = g_XW;
    int e = beg;
    for (; e + 1 < end; e += 2) {
        int s0 = g_csr[e], s1 = g_csr[e + 1];
        float c0 = g_dinv[s0], c1 = g_dinv[s1];
        float4 v0 = *(const float4*)(xw + (size_t)s0 * DH + t * 4);
        float4 v1 = *(const float4*)(xw + (size_t)s1 * DH + t * 4);
        ax += c0 * v0.x + c1 * v1.x;
        ay += c0 * v0.y + c1 * v1.y;
        az += c0 * v0.z + c1 * v1.z;
        aw += c0 * v0.w + c1 * v1.w;
    }
    if (e < end) {
        int s0 = g_csr[e];
        float c0 = g_dinv[s0];
        float4 v0 = *(const float4*)(xw + (size_t)s0 * DH + t * 4);
        ax += c0 * v0.x; ay += c0 * v0.y; az += c0 * v0.z; aw += c0 * v0.w;
    }
    float dd = g_dinv[g];
    float4 b = *(const float4*)(bias + t * 4);
    float rx = fmaxf(dd * ax + b.x, 0.f);
    float ry = fmaxf(dd * ay + b.y, 0.f);
    float rz = fmaxf(dd * az + b.z, 0.f);
    float rw = fmaxf(dd * aw + b.w, 0.f);

    if (mode == 0) {
        __nv_bfloat16 hx = __float2bfloat16(rx), hy = __float2bfloat16(ry);
        __nv_bfloat16 hz = __float2bfloat16(rz), hw = __float2bfloat16(rw);
        __nv_bfloat16 lx = __float2bfloat16(rx - __bfloat162float(hx));
        __nv_bfloat16 ly = __float2bfloat16(ry - __bfloat162float(hy));
        __nv_bfloat16 lz = __float2bfloat16(rz - __bfloat162float(hz));
        __nv_bfloat16 lw = __float2bfloat16(rw - __bfloat162float(hw));
        __nv_bfloat16* dst = g_A2 + (size_t)g * (2 * DH) + t * 4;
        *(__nv_bfloat162*)(dst)          = __halves2bfloat162(hx, hy);
        *(__nv_bfloat162*)(dst + 2)      = __halves2bfloat162(hz, hw);
        *(__nv_bfloat162*)(dst + DH)     = __halves2bfloat162(lx, ly);
        *(__nv_bfloat162*)(dst + DH + 2) = __halves2bfloat162(lz, lw);
    } else {
        *(float4*)(g_H2 + (size_t)g * DH + t * 4) = make_float4(rx, ry, rz, rw);
    }
}

// ---------------- pooling + fc head: out[g] = mean_{batch==g}(h2) @ w_fc + b_fc --------------
__global__ __launch_bounds__(256) void k_pool(const int* __restrict__ batch,
                                              const float* __restrict__ wfc,
                                              const float* __restrict__ bfc,
                                              float* __restrict__ out) {
    const int g = blockIdx.x;
    __shared__ int s_lo, s_hi;
    __shared__ float red[256];
    if (threadIdx.x == 0) {
        int lo = 0, hi = NN;
        while (lo < hi) { int m = (lo + hi) >> 1; if (batch[m] < g) lo = m + 1; else hi = m; }
        s_lo = lo;
        hi = NN;
        while (lo < hi) { int m = (lo + hi) >> 1; if (batch[m] < g + 1) lo = m + 1; else hi = m; }
        s_hi = lo;
    }
    __syncthreads();
    const int lo = s_lo, hi = s_hi;
    const int f = threadIdx.x;
    float acc = 0.f;
    for (int r = lo; r < hi; r++) acc += g_H2[(size_t)r * DH + f];
    float cnt = (float)((hi - lo) > 1 ? (hi - lo) : 1);
    red[f] = (acc / cnt) * wfc[f];
    __syncthreads();
    for (int off = 128; off > 0; off >>= 1) {
        if (f < off) red[f] += red[f + off];
        __syncthreads();
    }
    if (f == 0) out[g] = red[0] + bfc[0];
}

// ---------------- launch ----------------
extern "C" void kernel_launch(void* const* d_in, const int* in_sizes, int n_in,
                              void* d_out, int out_size) {
    const float* x    = (const float*)d_in[0];
    const int*   ei   = (const int*)d_in[1];   // [2, E]: row0 = src, row1 = dst
    const int*   bat  = (const int*)d_in[2];
    const float* W1   = (const float*)d_in[3];
    const float* b1   = (const float*)d_in[4];
    const float* W2   = (const float*)d_in[5];
    const float* b2   = (const float*)d_in[6];
    const float* wfc  = (const float*)d_in[7];
    const float* bfc  = (const float*)d_in[8];
    float* out = (float*)d_out;
    const int* src = ei;
    const int* dst = ei + EE;

    // one-time host-side resources (no device memory involved)
    static cudaStream_t s2 = nullptr;
    static cudaEvent_t evFork = nullptr, evJoin = nullptr;
    if (s2 == nullptr) {
        cudaStreamCreateWithFlags(&s2, cudaStreamNonBlocking);
        cudaEventCreateWithFlags(&evFork, cudaEventDisableTiming);
        cudaEventCreateWithFlags(&evJoin, cudaEventDisableTiming);
    }

    // ---- fork: CSR build (independent of the GEMM chain) on side stream ----
    cudaEventRecord(evFork, 0);
    cudaStreamWaitEvent(s2, evFork, 0);
    k_init<<<(NN + 255) / 256, 256, 0, s2>>>();
    k_count<<<(EE + 255) / 256, 256, 0, s2>>>(dst);
    k_scan<<<1, 1024, 0, s2>>>();
    k_fill<<<(EE + NN + 255) / 256, 256, 0, s2>>>(src, dst);
    cudaEventRecord(evJoin, s2);

    // ---- main stream: bf16 split operands + GEMM layer 1 ----
    k_convx<<<(NN * DIN / 4 + 255) / 256, 256>>>(x);
    k_wprep<<<(DIN * DH + 255) / 256, 256>>>(W1, 0);
    k_wprep<<<(DH * DH + 255) / 256, 256>>>(W2, 1);

    dim3 gg((NN + BM - 1) / BM, DH / BN);   // 157 x 2

    k_gemm<<<gg, 256>>>(0, NN);

    // join: aggregation needs both the CSR and XW
    cudaStreamWaitEvent(0, evJoin, 0);
    k_agg<<<NN / 4, 256>>>(b1, 0);

    // layer 2
    k_gemm<<<gg, 256>>>(1, NN);
    k_agg<<<NN / 4, 256>>>(b2, 1);

    // pooling + head
    k_pool<<<GG, 256>>>(bat, wfc, bfc, out);
}

// round 13
// speedup vs baseline: 1.5080x; 1.1710x over previous
#include <cuda_runtime.h>
#include <cuda_fp16.h>
#include <cstdint>

// Problem constants (fixed by the dataset)
#define NN   20000
#define EE   320000
#define DIN  512
#define DH   256
#define GG   128

// ---------------- device scratch (static allocation only) ----------------
__device__ int       g_deg[NN];
__device__ int       g_cursor[NN];
__device__ int       g_rowptr[NN + 1];
__device__ float     g_dinv[NN];
__device__ int       g_csr[EE + NN];
__device__ __half    g_A1[(size_t)NN * (2 * DIN)];   // [hi | lo] fp16 split of x
__device__ __half    g_A2[(size_t)NN * (2 * DH)];    // [hi | lo] fp16 split of h1
__device__ __half    g_W1h[(size_t)DIN * DH];        // fp16(W1), K-major
__device__ __half    g_W2h[(size_t)DH * DH];
__device__ float     g_XW[(size_t)NN * DH];          // GEMM output (reused both layers)
__device__ float     g_H2[(size_t)NN * DH];          // layer-2 node features

// ---------------- graph preprocessing ----------------
__global__ void k_init() {
    int i = blockIdx.x * blockDim.x + threadIdx.x;
    if (i < NN) { g_deg[i] = 1; g_cursor[i] = 0; }   // deg starts at 1 (self loop)
}

__global__ void k_count(const int* __restrict__ dst) {
    int e = blockIdx.x * blockDim.x + threadIdx.x;
    if (e < EE) atomicAdd(&g_deg[dst[e]], 1);
}

// single-block exclusive scan of g_deg -> g_rowptr, plus dinv = rsqrt(deg)
__global__ void k_scan() {
    __shared__ int partial[1024];
    const int tid = threadIdx.x;
    const int C = (NN + 1023) / 1024;   // 20
    int base = tid * C;
    int s = 0;
    for (int j = 0; j < C; j++) if (base + j < NN) s += g_deg[base + j];
    partial[tid] = s;
    __syncthreads();
    for (int off = 1; off < 1024; off <<= 1) {
        int v = (tid >= off) ? partial[tid - off] : 0;
        __syncthreads();
        partial[tid] += v;
        __syncthreads();
    }
    int run = partial[tid] - s;   // exclusive prefix for this chunk
    for (int j = 0; j < C; j++) {
        if (base + j < NN) {
            int d = g_deg[base + j];
            g_rowptr[base + j] = run;
            g_dinv[base + j] = rsqrtf((float)d);
            run += d;
        }
    }
    if (tid == 1023) g_rowptr[NN] = run;
}

__global__ void k_fill(const int* __restrict__ src, const int* __restrict__ dst) {
    int idx = blockIdx.x * blockDim.x + threadIdx.x;
    if (idx < EE) {
        int d = dst[idx];
        int pos = g_rowptr[d] + atomicAdd(&g_cursor[d], 1);
        g_csr[pos] = src[idx];
    } else if (idx < EE + NN) {
        int i = idx - EE;   // self loop
        int pos = g_rowptr[i] + atomicAdd(&g_cursor[i], 1);
        g_csr[pos] = i;
    }
}

// ---------------- fp16 hi/lo split conversions ----------------
__global__ void k_convx(const float* __restrict__ x) {
    int idx4 = blockIdx.x * blockDim.x + threadIdx.x;   // over NN*DIN/4
    if (idx4 >= NN * DIN / 4) return;
    int i = idx4 / (DIN / 4);
    int k = (idx4 % (DIN / 4)) * 4;
    float4 v = ((const float4*)x)[idx4];
    __half hx = __float2half(v.x), hy = __float2half(v.y);
    __half hz = __float2half(v.z), hw = __float2half(v.w);
    __half lx = __float2half(v.x - __half2float(hx));
    __half ly = __float2half(v.y - __half2float(hy));
    __half lz = __float2half(v.z - __half2float(hz));
    __half lw = __float2half(v.w - __half2float(hw));
    __half* base = g_A1 + (size_t)i * (2 * DIN);
    *(__half2*)(base + k)           = __halves2half2(hx, hy);
    *(__half2*)(base + k + 2)       = __halves2half2(hz, hw);
    *(__half2*)(base + DIN + k)     = __halves2half2(lx, ly);
    *(__half2*)(base + DIN + k + 2) = __halves2half2(lz, lw);
}

// W rounded once to fp16 (K-major, unchanged layout)
__global__ void k_wprep(const float* __restrict__ W, int layer) {
    const int K = (layer == 0) ? DIN : DH;
    __half* Wp = (layer == 0) ? g_W1h : g_W2h;
    int idx = blockIdx.x * blockDim.x + threadIdx.x;
    if (idx >= K * DH) return;
    Wp[idx] = __float2half(W[idx]);
}

// ---------------- fp16 GEMM: C[M,256] = [A_hi|A_lo] @ [W_h;W_h] ----------------
// logical K' = 2*Kb; both K-halves read the SAME W_h rows (no duplication).
#define BM 128
#define BN 128
#define BK 32
#define AP (BK + 8)    // 40 half row stride (conflict-free ldmatrix)
#define BP (BN + 8)    // 136

#define MMA16816(d, a, b0_, b1_)                                                  \
    asm volatile("mma.sync.aligned.m16n8k16.row.col.f32.f16.f16.f32 "             \
                 "{%0,%1,%2,%3}, {%4,%5,%6,%7}, {%8,%9}, {%0,%1,%2,%3};"          \
                 : "+f"((d)[0]), "+f"((d)[1]), "+f"((d)[2]), "+f"((d)[3])          \
                 : "r"((a)[0]), "r"((a)[1]), "r"((a)[2]), "r"((a)[3]),             \
                   "r"(b0_), "r"(b1_))

__global__ __launch_bounds__(256, 2) void k_gemm(int layer, int M) {
    const __half* __restrict__ A = (layer == 0) ? g_A1 : g_A2;
    const __half* __restrict__ B = (layer == 0) ? g_W1h : g_W2h;
    float* __restrict__ C = g_XW;
    const int Kb = (layer == 0) ? DIN : DH;

    __shared__ __align__(16) __half As[2][BM][AP];
    __shared__ __align__(16) __half Bs[2][BK][BP];

    const int tid  = threadIdx.x;
    const int lane = tid & 31;
    const int wid  = tid >> 5;
    const int wm   = wid & 3;    // 4 warps along M, 32 rows each
    const int wn   = wid >> 2;   // 2 warps along N, 64 cols each
    const int bm   = blockIdx.x * BM;
    const int bn   = blockIdx.y * BN;

    float c[2][8][4];
#pragma unroll
    for (int mt = 0; mt < 2; mt++)
#pragma unroll
        for (int nt = 0; nt < 8; nt++)
#pragma unroll
            for (int r = 0; r < 4; r++) c[mt][nt][r] = 0.f;

    auto load_stage = [&](int buf, int kt) {
        const int k0 = kt * BK;                 // logical K' offset (== physical A offset)
        const int kb = (k0 >= Kb) ? (k0 - Kb) : k0;   // W_h row base (shared by both halves)
#pragma unroll
        for (int j = 0; j < 2; j++) {
            int ch = tid + j * 256;
            // A chunk: 512 x 16B
            int ar = ch >> 2, ac = (ch & 3) * 8;
            const __half* asrc = A + (size_t)(bm + ar) * (2 * Kb) + k0 + ac;
            uint32_t adst = (uint32_t)__cvta_generic_to_shared(&As[buf][ar][ac]);
            int asz = (bm + ar < M) ? 16 : 0;
            asm volatile("cp.async.cg.shared.global [%0], [%1], 16, %2;\n"
                         :: "r"(adst), "l"(asrc), "r"(asz));
            // B chunk: 512 x 16B
            int br = ch >> 4, bc = (ch & 15) * 8;
            const __half* bsrc = B + (size_t)(kb + br) * DH + bn + bc;
            uint32_t bdst = (uint32_t)__cvta_generic_to_shared(&Bs[buf][br][bc]);
            asm volatile("cp.async.cg.shared.global [%0], [%1], 16, %2;\n"
                         :: "r"(bdst), "l"(bsrc), "r"(16));
        }
        asm volatile("cp.async.commit_group;\n");
    };

    const int KT = 2 * Kb / BK;
    load_stage(0, 0);

    for (int kt = 0; kt < KT; ++kt) {
        asm volatile("cp.async.wait_group 0;\n");
        __syncthreads();
        if (kt + 1 < KT) load_stage((kt + 1) & 1, kt + 1);
        const int buf = kt & 1;

#pragma unroll
        for (int kk = 0; kk < BK; kk += 16) {
            uint32_t a[2][4];
#pragma unroll
            for (int mt = 0; mt < 2; mt++) {
                const __half* p =
                    &As[buf][wm * 32 + mt * 16 + (lane & 15)][kk + (lane >> 4) * 8];
                uint32_t sp = (uint32_t)__cvta_generic_to_shared(p);
                asm volatile("ldmatrix.sync.aligned.m8n8.x4.shared.b16 {%0,%1,%2,%3}, [%4];"
                             : "=r"(a[mt][0]), "=r"(a[mt][1]), "=r"(a[mt][2]), "=r"(a[mt][3])
                             : "r"(sp));
            }
#pragma unroll
            for (int ng = 0; ng < 4; ++ng) {
                uint32_t bb[4];
                const __half* p =
                    &Bs[buf][kk + (lane & 15)][wn * 64 + ng * 16 + (lane >> 4) * 8];
                uint32_t sp = (uint32_t)__cvta_generic_to_shared(p);
                asm volatile("ldmatrix.sync.aligned.m8n8.x4.trans.shared.b16 {%0,%1,%2,%3}, [%4];"
                             : "=r"(bb[0]), "=r"(bb[1]), "=r"(bb[2]), "=r"(bb[3])
                             : "r"(sp));
#pragma unroll
                for (int mt = 0; mt < 2; mt++) {
                    MMA16816(c[mt][2 * ng],     a[mt], bb[0], bb[1]);
                    MMA16816(c[mt][2 * ng + 1], a[mt], bb[2], bb[3]);
                }
            }
        }
    }

    // epilogue
#pragma unroll
    for (int mt = 0; mt < 2; mt++) {
        int r0 = bm + wm * 32 + mt * 16 + (lane >> 2);
#pragma unroll
        for (int nt = 0; nt < 8; nt++) {
            int col = bn + wn * 64 + nt * 8 + (lane & 3) * 2;
            if (r0 < M)
                *(float2*)&C[(size_t)r0 * DH + col] = make_float2(c[mt][nt][0], c[mt][nt][1]);
            if (r0 + 8 < M)
                *(float2*)&C[(size_t)(r0 + 8) * DH + col] = make_float2(c[mt][nt][2], c[mt][nt][3]);
        }
    }
}

// ---------------- aggregation: out[d] = relu(dinv[d]*sum_{s in N(d)} dinv[s]*XW[s] + b) --------
// mode 0: emit fp16 [hi|lo] into g_A2 (feeds GEMM2).  mode 1: emit f32 into g_H2.
__global__ __launch_bounds__(256) void k_agg(const float* __restrict__ bias, int mode) {
    int g = blockIdx.x * 4 + (threadIdx.x >> 6);   // dst node
    int t = threadIdx.x & 63;                      // owns features [4t, 4t+4)
    if (g >= NN) return;
    const int beg = g_rowptr[g], end = g_rowptr[g + 1];
    float ax = 0.f, ay = 0.f, az = 0.f, aw = 0.f;
    const float* __restrict__ xw = g_XW;
    int e = beg;
    for (; e + 1 < end; e += 2) {
        int s0 = g_csr[e], s1 = g_csr[e + 1];
        float c0 = g_dinv[s0], c1 = g_dinv[s1];
        float4 v0 = *(const float4*)(xw + (size_t)s0 * DH + t * 4);
        float4 v1 = *(const float4*)(xw + (size_t)s1 * DH + t * 4);
        ax += c0 * v0.x + c1 * v1.x;
        ay += c0 * v0.y + c1 * v1.y;
        az += c0 * v0.z + c1 * v1.z;
        aw += c0 * v0.w + c1 * v1.w;
    }
    if (e < end) {
        int s0 = g_csr[e];
        float c0 = g_dinv[s0];
        float4 v0 = *(const float4*)(xw + (size_t)s0 * DH + t * 4);
        ax += c0 * v0.x; ay += c0 * v0.y; az += c0 * v0.z; aw += c0 * v0.w;
    }
    float dd = g_dinv[g];
    float4 b = *(const float4*)(bias + t * 4);
    float rx = fmaxf(dd * ax + b.x, 0.f);
    float ry = fmaxf(dd * ay + b.y, 0.f);
    float rz = fmaxf(dd * az + b.z, 0.f);
    float rw = fmaxf(dd * aw + b.w, 0.f);

    if (mode == 0) {
        __half hx = __float2half(rx), hy = __float2half(ry);
        __half hz = __float2half(rz), hw = __float2half(rw);
        __half lx = __float2half(rx - __half2float(hx));
        __half ly = __float2half(ry - __half2float(hy));
        __half lz = __float2half(rz - __half2float(hz));
        __half lw = __float2half(rw - __half2float(hw));
        __half* dst = g_A2 + (size_t)g * (2 * DH) + t * 4;
        *(__half2*)(dst)          = __halves2half2(hx, hy);
        *(__half2*)(dst + 2)      = __halves2half2(hz, hw);
        *(__half2*)(dst + DH)     = __halves2half2(lx, ly);
        *(__half2*)(dst + DH + 2) = __halves2half2(lz, lw);
    } else {
        *(float4*)(g_H2 + (size_t)g * DH + t * 4) = make_float4(rx, ry, rz, rw);
    }
}

// ---------------- pooling + fc head: out[g] = mean_{batch==g}(h2) @ w_fc + b_fc --------------
__global__ __launch_bounds__(256) void k_pool(const int* __restrict__ batch,
                                              const float* __restrict__ wfc,
                                              const float* __restrict__ bfc,
                                              float* __restrict__ out) {
    const int g = blockIdx.x;
    __shared__ int s_lo, s_hi;
    __shared__ float red[256];
    if (threadIdx.x == 0) {
        int lo = 0, hi = NN;
        while (lo < hi) { int m = (lo + hi) >> 1; if (batch[m] < g) lo = m + 1; else hi = m; }
        s_lo = lo;
        hi = NN;
        while (lo < hi) { int m = (lo + hi) >> 1; if (batch[m] < g + 1) lo = m + 1; else hi = m; }
        s_hi = lo;
    }
    __syncthreads();
    const int lo = s_lo, hi = s_hi;
    const int f = threadIdx.x;
    float acc = 0.f;
    for (int r = lo; r < hi; r++) acc += g_H2[(size_t)r * DH + f];
    float cnt = (float)((hi - lo) > 1 ? (hi - lo) : 1);
    red[f] = (acc / cnt) * wfc[f];
    __syncthreads();
    for (int off = 128; off > 0; off >>= 1) {
        if (f < off) red[f] += red[f + off];
        __syncthreads();
    }
    if (f == 0) out[g] = red[0] + bfc[0];
}

// ---------------- launch ----------------
extern "C" void kernel_launch(void* const* d_in, const int* in_sizes, int n_in,
                              void* d_out, int out_size) {
    const float* x    = (const float*)d_in[0];
    const int*   ei   = (const int*)d_in[1];   // [2, E]: row0 = src, row1 = dst
    const int*   bat  = (const int*)d_in[2];
    const float* W1   = (const float*)d_in[3];
    const float* b1   = (const float*)d_in[4];
    const float* W2   = (const float*)d_in[5];
    const float* b2   = (const float*)d_in[6];
    const float* wfc  = (const float*)d_in[7];
    const float* bfc  = (const float*)d_in[8];
    float* out = (float*)d_out;
    const int* src = ei;
    const int* dst = ei + EE;

    // one-time host-side resources (no device memory involved)
    static cudaStream_t s2 = nullptr;
    static cudaEvent_t evFork = nullptr, evJoin = nullptr;
    if (s2 == nullptr) {
        cudaStreamCreateWithFlags(&s2, cudaStreamNonBlocking);
        cudaEventCreateWithFlags(&evFork, cudaEventDisableTiming);
        cudaEventCreateWithFlags(&evJoin, cudaEventDisableTiming);
    }

    // ---- fork: CSR build (independent of the GEMM chain) on side stream ----
    cudaEventRecord(evFork, 0);
    cudaStreamWaitEvent(s2, evFork, 0);
    k_init<<<(NN + 255) / 256, 256, 0, s2>>>();
    k_count<<<(EE + 255) / 256, 256, 0, s2>>>(dst);
    k_scan<<<1, 1024, 0, s2>>>();
    k_fill<<<(EE + NN + 255) / 256, 256, 0, s2>>>(src, dst);
    cudaEventRecord(evJoin, s2);

    // ---- main stream: fp16 split operands + GEMM layer 1 ----
    k_convx<<<(NN * DIN / 4 + 255) / 256, 256>>>(x);
    k_wprep<<<(DIN * DH + 255) / 256, 256>>>(W1, 0);
    k_wprep<<<(DH * DH + 255) / 256, 256>>>(W2, 1);

    dim3 gg((NN + BM - 1) / BM, DH / BN);   // 157 x 2

    k_gemm<<<gg, 256>>>(0, NN);

    // join: aggregation needs both the CSR and XW
    cudaStreamWaitEvent(0, evJoin, 0);
    k_agg<<<NN / 4, 256>>>(b1, 0);

    // layer 2
    k_gemm<<<gg, 256>>>(1, NN);
    k_agg<<<NN / 4, 256>>>(b2, 1);

    // pooling + head
    k_pool<<<GG, 256>>>(bat, wfc, bfc, out);
}

// round 14
// speedup vs baseline: 1.8244x; 1.2098x over previous
#include <cuda_runtime.h>
#include <cuda_fp16.h>
#include <cstdint>

// Problem constants (fixed by the dataset)
#define NN   20000
#define EE   320000
#define DIN  512
#define DH   256
#define GG   128

// ---------------- device scratch (static allocation only) ----------------
__device__ int       g_deg[NN];
__device__ int       g_cursor[NN];
__device__ int       g_rowptr[NN + 1];
__device__ float     g_dinv[NN];
__device__ int       g_csr[EE + NN];
__device__ __half    g_A1[(size_t)NN * DIN];   // fp16(x)
__device__ __half    g_A2[(size_t)NN * DH];    // fp16(h1) (written by agg1)
__device__ __half    g_W1h[(size_t)DIN * DH];  // fp16(W1), K-major
__device__ __half    g_W2h[(size_t)DH * DH];
__device__ float     g_XW[(size_t)NN * DH];    // GEMM output (reused both layers)
__device__ float     g_H2[(size_t)NN * DH];    // layer-2 node features

// ---------------- graph preprocessing ----------------
__global__ void k_init() {
    int i = blockIdx.x * blockDim.x + threadIdx.x;
    if (i < NN) { g_deg[i] = 1; g_cursor[i] = 0; }   // deg starts at 1 (self loop)
}

__global__ void k_count(const int* __restrict__ dst) {
    int e = blockIdx.x * blockDim.x + threadIdx.x;
    if (e < EE) atomicAdd(&g_deg[dst[e]], 1);
}

// single-block exclusive scan of g_deg -> g_rowptr, plus dinv = rsqrt(deg)
__global__ void k_scan() {
    __shared__ int partial[1024];
    const int tid = threadIdx.x;
    const int C = (NN + 1023) / 1024;   // 20
    int base = tid * C;
    int s = 0;
    for (int j = 0; j < C; j++) if (base + j < NN) s += g_deg[base + j];
    partial[tid] = s;
    __syncthreads();
    for (int off = 1; off < 1024; off <<= 1) {
        int v = (tid >= off) ? partial[tid - off] : 0;
        __syncthreads();
        partial[tid] += v;
        __syncthreads();
    }
    int run = partial[tid] - s;   // exclusive prefix for this chunk
    for (int j = 0; j < C; j++) {
        if (base + j < NN) {
            int d = g_deg[base + j];
            g_rowptr[base + j] = run;
            g_dinv[base + j] = rsqrtf((float)d);
            run += d;
        }
    }
    if (tid == 1023) g_rowptr[NN] = run;
}

__global__ void k_fill(const int* __restrict__ src, const int* __restrict__ dst) {
    int idx = blockIdx.x * blockDim.x + threadIdx.x;
    if (idx < EE) {
        int d = dst[idx];
        int pos = g_rowptr[d] + atomicAdd(&g_cursor[d], 1);
        g_csr[pos] = src[idx];
    } else if (idx < EE + NN) {
        int i = idx - EE;   // self loop
        int pos = g_rowptr[i] + atomicAdd(&g_cursor[i], 1);
        g_csr[pos] = i;
    }
}

// ---------------- fp16 conversions ----------------
__global__ void k_convx(const float* __restrict__ x) {
    int idx4 = blockIdx.x * blockDim.x + threadIdx.x;   // over NN*DIN/4
    if (idx4 >= NN * DIN / 4) return;
    float4 v = ((const float4*)x)[idx4];
    __half2 a = __halves2half2(__float2half(v.x), __float2half(v.y));
    __half2 b = __halves2half2(__float2half(v.z), __float2half(v.w));
    ((__half2*)g_A1)[idx4 * 2]     = a;
    ((__half2*)g_A1)[idx4 * 2 + 1] = b;
}

// W rounded once to fp16 (K-major, unchanged layout)
__global__ void k_wprep(const float* __restrict__ W, int layer) {
    const int K = (layer == 0) ? DIN : DH;
    __half* Wp = (layer == 0) ? g_W1h : g_W2h;
    int idx = blockIdx.x * blockDim.x + threadIdx.x;
    if (idx >= K * DH) return;
    Wp[idx] = __float2half(W[idx]);
}

// ---------------- fp16 GEMM: C[M,256] = A[M,Kb] @ W[Kb,256] ----------------
#define BM 128
#define BN 128
#define BK 32
#define AP (BK + 8)    // 40 half row stride (conflict-free ldmatrix)
#define BP (BN + 8)    // 136

#define MMA16816(d, a, b0_, b1_)                                                  \
    asm volatile("mma.sync.aligned.m16n8k16.row.col.f32.f16.f16.f32 "             \
                 "{%0,%1,%2,%3}, {%4,%5,%6,%7}, {%8,%9}, {%0,%1,%2,%3};"          \
                 : "+f"((d)[0]), "+f"((d)[1]), "+f"((d)[2]), "+f"((d)[3])          \
                 : "r"((a)[0]), "r"((a)[1]), "r"((a)[2]), "r"((a)[3]),             \
                   "r"(b0_), "r"(b1_))

__global__ __launch_bounds__(256, 2) void k_gemm(int layer, int M) {
    const __half* __restrict__ A = (layer == 0) ? g_A1 : g_A2;
    const __half* __restrict__ B = (layer == 0) ? g_W1h : g_W2h;
    float* __restrict__ C = g_XW;
    const int Kb = (layer == 0) ? DIN : DH;

    __shared__ __align__(16) __half As[2][BM][AP];
    __shared__ __align__(16) __half Bs[2][BK][BP];

    const int tid  = threadIdx.x;
    const int lane = tid & 31;
    const int wid  = tid >> 5;
    const int wm   = wid & 3;    // 4 warps along M, 32 rows each
    const int wn   = wid >> 2;   // 2 warps along N, 64 cols each
    const int bm   = blockIdx.x * BM;
    const int bn   = blockIdx.y * BN;

    float c[2][8][4];
#pragma unroll
    for (int mt = 0; mt < 2; mt++)
#pragma unroll
        for (int nt = 0; nt < 8; nt++)
#pragma unroll
            for (int r = 0; r < 4; r++) c[mt][nt][r] = 0.f;

    auto load_stage = [&](int buf, int kt) {
        const int k0 = kt * BK;
#pragma unroll
        for (int j = 0; j < 2; j++) {
            int ch = tid + j * 256;
            // A chunk: 512 x 16B
            int ar = ch >> 2, ac = (ch & 3) * 8;
            const __half* asrc = A + (size_t)(bm + ar) * Kb + k0 + ac;
            uint32_t adst = (uint32_t)__cvta_generic_to_shared(&As[buf][ar][ac]);
            int asz = (bm + ar < M) ? 16 : 0;
            asm volatile("cp.async.cg.shared.global [%0], [%1], 16, %2;\n"
                         :: "r"(adst), "l"(asrc), "r"(asz));
            // B chunk: 512 x 16B
            int br = ch >> 4, bc = (ch & 15) * 8;
            const __half* bsrc = B + (size_t)(k0 + br) * DH + bn + bc;
            uint32_t bdst = (uint32_t)__cvta_generic_to_shared(&Bs[buf][br][bc]);
            asm volatile("cp.async.cg.shared.global [%0], [%1], 16, %2;\n"
                         :: "r"(bdst), "l"(bsrc), "r"(16));
        }
        asm volatile("cp.async.commit_group;\n");
    };

    const int KT = Kb / BK;
    load_stage(0, 0);

    for (int kt = 0; kt < KT; ++kt) {
        asm volatile("cp.async.wait_group 0;\n");
        __syncthreads();
        if (kt + 1 < KT) load_stage((kt + 1) & 1, kt + 1);
        const int buf = kt & 1;

#pragma unroll
        for (int kk = 0; kk < BK; kk += 16) {
            uint32_t a[2][4];
#pragma unroll
            for (int mt = 0; mt < 2; mt++) {
                const __half* p =
                    &As[buf][wm * 32 + mt * 16 + (lane & 15)][kk + (lane >> 4) * 8];
                uint32_t sp = (uint32_t)__cvta_generic_to_shared(p);
                asm volatile("ldmatrix.sync.aligned.m8n8.x4.shared.b16 {%0,%1,%2,%3}, [%4];"
                             : "=r"(a[mt][0]), "=r"(a[mt][1]), "=r"(a[mt][2]), "=r"(a[mt][3])
                             : "r"(sp));
            }
#pragma unroll
            for (int ng = 0; ng < 4; ++ng) {
                uint32_t bb[4];
                const __half* p =
                    &Bs[buf][kk + (lane & 15)][wn * 64 + ng * 16 + (lane >> 4) * 8];
                uint32_t sp = (uint32_t)__cvta_generic_to_shared(p);
                asm volatile("ldmatrix.sync.aligned.m8n8.x4.trans.shared.b16 {%0,%1,%2,%3}, [%4];"
                             : "=r"(bb[0]), "=r"(bb[1]), "=r"(bb[2]), "=r"(bb[3])
                             : "r"(sp));
#pragma unroll
                for (int mt = 0; mt < 2; mt++) {
                    MMA16816(c[mt][2 * ng],     a[mt], bb[0], bb[1]);
                    MMA16816(c[mt][2 * ng + 1], a[mt], bb[2], bb[3]);
                }
            }
        }
    }

    // epilogue
#pragma unroll
    for (int mt = 0; mt < 2; mt++) {
        int r0 = bm + wm * 32 + mt * 16 + (lane >> 2);
#pragma unroll
        for (int nt = 0; nt < 8; nt++) {
            int col = bn + wn * 64 + nt * 8 + (lane & 3) * 2;
            if (r0 < M)
                *(float2*)&C[(size_t)r0 * DH + col] = make_float2(c[mt][nt][0], c[mt][nt][1]);
            if (r0 + 8 < M)
                *(float2*)&C[(size_t)(r0 + 8) * DH + col] = make_float2(c[mt][nt][2], c[mt][nt][3]);
        }
    }
}

// ---------------- aggregation: out[d] = relu(dinv[d]*sum_{s in N(d)} dinv[s]*XW[s] + b) --------
// mode 0: emit fp16 into g_A2 (feeds GEMM2).  mode 1: emit f32 into g_H2.
__global__ __launch_bounds__(256) void k_agg(const float* __restrict__ bias, int mode) {
    int g = blockIdx.x * 4 + (threadIdx.x >> 6);   // dst node
    int t = threadIdx.x & 63;                      // owns features [4t, 4t+4)
    if (g >= NN) return;
    const int beg = g_rowptr[g], end = g_rowptr[g + 1];
    float ax = 0.f, ay = 0.f, az = 0.f, aw = 0.f;
    const float* __restrict__ xw = g_XW;
    int e = beg;
    for (; e + 1 < end; e += 2) {
        int s0 = g_csr[e], s1 = g_csr[e + 1];
        float c0 = g_dinv[s0], c1 = g_dinv[s1];
        float4 v0 = *(const float4*)(xw + (size_t)s0 * DH + t * 4);
        float4 v1 = *(const float4*)(xw + (size_t)s1 * DH + t * 4);
        ax += c0 * v0.x + c1 * v1.x;
        ay += c0 * v0.y + c1 * v1.y;
        az += c0 * v0.z + c1 * v1.z;
        aw += c0 * v0.w + c1 * v1.w;
    }
    if (e < end) {
        int s0 = g_csr[e];
        float c0 = g_dinv[s0];
        float4 v0 = *(const float4*)(xw + (size_t)s0 * DH + t * 4);
        ax += c0 * v0.x; ay += c0 * v0.y; az += c0 * v0.z; aw += c0 * v0.w;
    }
    float dd = g_dinv[g];
    float4 b = *(const float4*)(bias + t * 4);
    float rx = fmaxf(dd * ax + b.x, 0.f);
    float ry = fmaxf(dd * ay + b.y, 0.f);
    float rz = fmaxf(dd * az + b.z, 0.f);
    float rw = fmaxf(dd * aw + b.w, 0.f);

    if (mode == 0) {
        __half2 p0 = __halves2half2(__float2half(rx), __float2half(ry));
        __half2 p1 = __halves2half2(__float2half(rz), __float2half(rw));
        __half* dst = g_A2 + (size_t)g * DH + t * 4;
        *(__half2*)(dst)     = p0;
        *(__half2*)(dst + 2) = p1;
    } else {
        *(float4*)(g_H2 + (size_t)g * DH + t * 4) = make_float4(rx, ry, rz, rw);
    }
}

// ---------------- pooling + fc head: out[g] = mean_{batch==g}(h2) @ w_fc + b_fc --------------
__global__ __launch_bounds__(256) void k_pool(const int* __restrict__ batch,
                                              const float* __restrict__ wfc,
                                              const float* __restrict__ bfc,
                                              float* __restrict__ out) {
    const int g = blockIdx.x;
    __shared__ int s_lo, s_hi;
    __shared__ float red[256];
    if (threadIdx.x == 0) {
        int lo = 0, hi = NN;
        while (lo < hi) { int m = (lo + hi) >> 1; if (batch[m] < g) lo = m + 1; else hi = m; }
        s_lo = lo;
        hi = NN;
        while (lo < hi) { int m = (lo + hi) >> 1; if (batch[m] < g + 1) lo = m + 1; else hi = m; }
        s_hi = lo;
    }
    __syncthreads();
    const int lo = s_lo, hi = s_hi;
    const int f = threadIdx.x;
    float acc = 0.f;
    for (int r = lo; r < hi; r++) acc += g_H2[(size_t)r * DH + f];
    float cnt = (float)((hi - lo) > 1 ? (hi - lo) : 1);
    red[f] = (acc / cnt) * wfc[f];
    __syncthreads();
    for (int off = 128; off > 0; off >>= 1) {
        if (f < off) red[f] += red[f + off];
        __syncthreads();
    }
    if (f == 0) out[g] = red[0] + bfc[0];
}

// ---------------- launch ----------------
extern "C" void kernel_launch(void* const* d_in, const int* in_sizes, int n_in,
                              void* d_out, int out_size) {
    const float* x    = (const float*)d_in[0];
    const int*   ei   = (const int*)d_in[1];   // [2, E]: row0 = src, row1 = dst
    const int*   bat  = (const int*)d_in[2];
    const float* W1   = (const float*)d_in[3];
    const float* b1   = (const float*)d_in[4];
    const float* W2   = (const float*)d_in[5];
    const float* b2   = (const float*)d_in[6];
    const float* wfc  = (const float*)d_in[7];
    const float* bfc  = (const float*)d_in[8];
    float* out = (float*)d_out;
    const int* src = ei;
    const int* dst = ei + EE;

    // one-time host-side resources (no device memory involved)
    static cudaStream_t s2 = nullptr;
    static cudaEvent_t evFork = nullptr, evJoin = nullptr;
    if (s2 == nullptr) {
        cudaStreamCreateWithFlags(&s2, cudaStreamNonBlocking);
        cudaEventCreateWithFlags(&evFork, cudaEventDisableTiming);
        cudaEventCreateWithFlags(&evJoin, cudaEventDisableTiming);
    }

    // ---- fork: CSR build (independent of the GEMM chain) on side stream ----
    cudaEventRecord(evFork, 0);
    cudaStreamWaitEvent(s2, evFork, 0);
    k_init<<<(NN + 255) / 256, 256, 0, s2>>>();
    k_count<<<(EE + 255) / 256, 256, 0, s2>>>(dst);
    k_scan<<<1, 1024, 0, s2>>>();
    k_fill<<<(EE + NN + 255) / 256, 256, 0, s2>>>(src, dst);
    cudaEventRecord(evJoin, s2);

    // ---- main stream: fp16 operands + GEMM layer 1 ----
    k_convx<<<(NN * DIN / 4 + 255) / 256, 256>>>(x);
    k_wprep<<<(DIN * DH + 255) / 256, 256>>>(W1, 0);
    k_wprep<<<(DH * DH + 255) / 256, 256>>>(W2, 1);

    dim3 gg((NN + BM - 1) / BM, DH / BN);   // 157 x 2

    k_gemm<<<gg, 256>>>(0, NN);

    // join: aggregation needs both the CSR and XW
    cudaStreamWaitEvent(0, evJoin, 0);
    k_agg<<<NN / 4, 256>>>(b1, 0);

    // layer 2
    k_gemm<<<gg, 256>>>(1, NN);
    k_agg<<<NN / 4, 256>>>(b2, 1);

    // pooling + head
    k_pool<<<GG, 256>>>(bat, wfc, bfc, out);
}

// round 15
// speedup vs baseline: 2.0903x; 1.1458x over previous
#include <cuda_runtime.h>
#include <cuda_fp16.h>
#include <cstdint>

// Problem constants (fixed by the dataset)
#define NN   20000
#define EE   320000
#define DIN  512
#define DH   256
#define GG   128

// ---------------- device scratch (static allocation only) ----------------
__device__ int       g_deg[NN];
__device__ int       g_cursor[NN];
__device__ int       g_rowptr[NN + 1];
__device__ float     g_dinv[NN];
__device__ int       g_csr[EE + NN];
__device__ __half    g_A1[(size_t)NN * DIN];   // fp16(x)
__device__ __half    g_A2[(size_t)NN * DH];    // fp16(h1) (written by agg1)
__device__ __half    g_W1h[(size_t)DIN * DH];  // fp16(W1), K-major
__device__ __half    g_W2h[(size_t)DH * DH];
__device__ __half    g_XWh[(size_t)NN * DH];   // GEMM output, fp16 (reused both layers)
__device__ __half    g_H2h[(size_t)NN * DH];   // layer-2 node features, fp16

// ---------------- graph preprocessing ----------------
__global__ void k_init() {
    int i = blockIdx.x * blockDim.x + threadIdx.x;
    if (i < NN) { g_deg[i] = 1; g_cursor[i] = 0; }   // deg starts at 1 (self loop)
}

__global__ void k_count(const int* __restrict__ dst) {
    int e = blockIdx.x * blockDim.x + threadIdx.x;
    if (e < EE) atomicAdd(&g_deg[dst[e]], 1);
}

// single-block exclusive scan of g_deg -> g_rowptr, plus dinv = rsqrt(deg)
__global__ void k_scan() {
    __shared__ int partial[1024];
    const int tid = threadIdx.x;
    const int C = (NN + 1023) / 1024;   // 20
    int base = tid * C;
    int s = 0;
    for (int j = 0; j < C; j++) if (base + j < NN) s += g_deg[base + j];
    partial[tid] = s;
    __syncthreads();
    for (int off = 1; off < 1024; off <<= 1) {
        int v = (tid >= off) ? partial[tid - off] : 0;
        __syncthreads();
        partial[tid] += v;
        __syncthreads();
    }
    int run = partial[tid] - s;   // exclusive prefix for this chunk
    for (int j = 0; j < C; j++) {
        if (base + j < NN) {
            int d = g_deg[base + j];
            g_rowptr[base + j] = run;
            g_dinv[base + j] = rsqrtf((float)d);
            run += d;
        }
    }
    if (tid == 1023) g_rowptr[NN] = run;
}

__global__ void k_fill(const int* __restrict__ src, const int* __restrict__ dst) {
    int idx = blockIdx.x * blockDim.x + threadIdx.x;
    if (idx < EE) {
        int d = dst[idx];
        int pos = g_rowptr[d] + atomicAdd(&g_cursor[d], 1);
        g_csr[pos] = src[idx];
    } else if (idx < EE + NN) {
        int i = idx - EE;   // self loop
        int pos = g_rowptr[i] + atomicAdd(&g_cursor[i], 1);
        g_csr[pos] = i;
    }
}

// ---------------- fp16 conversions ----------------
__global__ void k_convx(const float* __restrict__ x) {
    int idx4 = blockIdx.x * blockDim.x + threadIdx.x;   // over NN*DIN/4
    if (idx4 >= NN * DIN / 4) return;
    float4 v = ((const float4*)x)[idx4];
    __half2 a = __halves2half2(__float2half(v.x), __float2half(v.y));
    __half2 b = __halves2half2(__float2half(v.z), __float2half(v.w));
    ((__half2*)g_A1)[idx4 * 2]     = a;
    ((__half2*)g_A1)[idx4 * 2 + 1] = b;
}

// W rounded once to fp16 (K-major, unchanged layout)
__global__ void k_wprep(const float* __restrict__ W, int layer) {
    const int K = (layer == 0) ? DIN : DH;
    __half* Wp = (layer == 0) ? g_W1h : g_W2h;
    int idx = blockIdx.x * blockDim.x + threadIdx.x;
    if (idx >= K * DH) return;
    Wp[idx] = __float2half(W[idx]);
}

// ---------------- fp16 GEMM: C[M,256] = A[M,Kb] @ W[Kb,256], fp16 out ----------------
#define BM 128
#define BN 128
#define BK 32
#define AP (BK + 8)    // 40 half row stride (conflict-free ldmatrix)
#define BP (BN + 8)    // 136

#define MMA16816(d, a, b0_, b1_)                                                  \
    asm volatile("mma.sync.aligned.m16n8k16.row.col.f32.f16.f16.f32 "             \
                 "{%0,%1,%2,%3}, {%4,%5,%6,%7}, {%8,%9}, {%0,%1,%2,%3};"          \
                 : "+f"((d)[0]), "+f"((d)[1]), "+f"((d)[2]), "+f"((d)[3])          \
                 : "r"((a)[0]), "r"((a)[1]), "r"((a)[2]), "r"((a)[3]),             \
                   "r"(b0_), "r"(b1_))

__global__ __launch_bounds__(256, 2) void k_gemm(int layer, int M) {
    const __half* __restrict__ A = (layer == 0) ? g_A1 : g_A2;
    const __half* __restrict__ B = (layer == 0) ? g_W1h : g_W2h;
    __half* __restrict__ C = g_XWh;
    const int Kb = (layer == 0) ? DIN : DH;

    __shared__ __align__(16) __half As[2][BM][AP];
    __shared__ __align__(16) __half Bs[2][BK][BP];

    const int tid  = threadIdx.x;
    const int lane = tid & 31;
    const int wid  = tid >> 5;
    const int wm   = wid & 3;    // 4 warps along M, 32 rows each
    const int wn   = wid >> 2;   // 2 warps along N, 64 cols each
    const int bm   = blockIdx.x * BM;
    const int bn   = blockIdx.y * BN;

    float c[2][8][4];
#pragma unroll
    for (int mt = 0; mt < 2; mt++)
#pragma unroll
        for (int nt = 0; nt < 8; nt++)
#pragma unroll
            for (int r = 0; r < 4; r++) c[mt][nt][r] = 0.f;

    auto load_stage = [&](int buf, int kt) {
        const int k0 = kt * BK;
#pragma unroll
        for (int j = 0; j < 2; j++) {
            int ch = tid + j * 256;
            // A chunk: 512 x 16B
            int ar = ch >> 2, ac = (ch & 3) * 8;
            const __half* asrc = A + (size_t)(bm + ar) * Kb + k0 + ac;
            uint32_t adst = (uint32_t)__cvta_generic_to_shared(&As[buf][ar][ac]);
            int asz = (bm + ar < M) ? 16 : 0;
            asm volatile("cp.async.cg.shared.global [%0], [%1], 16, %2;\n"
                         :: "r"(adst), "l"(asrc), "r"(asz));
            // B chunk: 512 x 16B
            int br = ch >> 4, bc = (ch & 15) * 8;
            const __half* bsrc = B + (size_t)(k0 + br) * DH + bn + bc;
            uint32_t bdst = (uint32_t)__cvta_generic_to_shared(&Bs[buf][br][bc]);
            asm volatile("cp.async.cg.shared.global [%0], [%1], 16, %2;\n"
                         :: "r"(bdst), "l"(bsrc), "r"(16));
        }
        asm volatile("cp.async.commit_group;\n");
    };

    const int KT = Kb / BK;
    load_stage(0, 0);

    for (int kt = 0; kt < KT; ++kt) {
        asm volatile("cp.async.wait_group 0;\n");
        __syncthreads();
        if (kt + 1 < KT) load_stage((kt + 1) & 1, kt + 1);
        const int buf = kt & 1;

#pragma unroll
        for (int kk = 0; kk < BK; kk += 16) {
            uint32_t a[2][4];
#pragma unroll
            for (int mt = 0; mt < 2; mt++) {
                const __half* p =
                    &As[buf][wm * 32 + mt * 16 + (lane & 15)][kk + (lane >> 4) * 8];
                uint32_t sp = (uint32_t)__cvta_generic_to_shared(p);
                asm volatile("ldmatrix.sync.aligned.m8n8.x4.shared.b16 {%0,%1,%2,%3}, [%4];"
                             : "=r"(a[mt][0]), "=r"(a[mt][1]), "=r"(a[mt][2]), "=r"(a[mt][3])
                             : "r"(sp));
            }
#pragma unroll
            for (int ng = 0; ng < 4; ++ng) {
                uint32_t bb[4];
                const __half* p =
                    &Bs[buf][kk + (lane & 15)][wn * 64 + ng * 16 + (lane >> 4) * 8];
                uint32_t sp = (uint32_t)__cvta_generic_to_shared(p);
                asm volatile("ldmatrix.sync.aligned.m8n8.x4.trans.shared.b16 {%0,%1,%2,%3}, [%4];"
                             : "=r"(bb[0]), "=r"(bb[1]), "=r"(bb[2]), "=r"(bb[3])
                             : "r"(sp));
#pragma unroll
                for (int mt = 0; mt < 2; mt++) {
                    MMA16816(c[mt][2 * ng],     a[mt], bb[0], bb[1]);
                    MMA16816(c[mt][2 * ng + 1], a[mt], bb[2], bb[3]);
                }
            }
        }
    }

    // epilogue: fp16 stores
#pragma unroll
    for (int mt = 0; mt < 2; mt++) {
        int r0 = bm + wm * 32 + mt * 16 + (lane >> 2);
#pragma unroll
        for (int nt = 0; nt < 8; nt++) {
            int col = bn + wn * 64 + nt * 8 + (lane & 3) * 2;
            if (r0 < M)
                *(__half2*)&C[(size_t)r0 * DH + col] =
                    __floats2half2_rn(c[mt][nt][0], c[mt][nt][1]);
            if (r0 + 8 < M)
                *(__half2*)&C[(size_t)(r0 + 8) * DH + col] =
                    __floats2half2_rn(c[mt][nt][2], c[mt][nt][3]);
        }
    }
}

// ---------------- aggregation: out[d] = relu(dinv[d]*sum_{s in N(d)} dinv[s]*XW[s] + b) --------
// XW fp16 in, fp32 accumulate, fp16 out. mode 0 -> g_A2 (feeds GEMM2), mode 1 -> g_H2h (pool).
__global__ __launch_bounds__(256) void k_agg(const float* __restrict__ bias, int mode) {
    const int g = blockIdx.x * 8 + (threadIdx.x >> 5);   // dst node (one warp per node)
    const int t = threadIdx.x & 31;                      // owns features [8t, 8t+8)
    if (g >= NN) return;
    const int beg = g_rowptr[g], end = g_rowptr[g + 1];
    float acc[8];
#pragma unroll
    for (int i = 0; i < 8; i++) acc[i] = 0.f;
    const __half* __restrict__ xw = g_XWh;

    int e = beg;
    for (; e + 1 < end; e += 2) {
        int s0 = g_csr[e], s1 = g_csr[e + 1];
        float c0 = g_dinv[s0], c1 = g_dinv[s1];
        uint4 p0 = *(const uint4*)(xw + (size_t)s0 * DH + t * 8);
        uint4 p1 = *(const uint4*)(xw + (size_t)s1 * DH + t * 8);
        const __half2* h0 = (const __half2*)&p0;
        const __half2* h1 = (const __half2*)&p1;
#pragma unroll
        for (int i = 0; i < 4; i++) {
            float2 f0 = __half22float2(h0[i]);
            float2 f1 = __half22float2(h1[i]);
            acc[2 * i]     += c0 * f0.x + c1 * f1.x;
            acc[2 * i + 1] += c0 * f0.y + c1 * f1.y;
        }
    }
    if (e < end) {
        int s0 = g_csr[e];
        float c0 = g_dinv[s0];
        uint4 p0 = *(const uint4*)(xw + (size_t)s0 * DH + t * 8);
        const __half2* h0 = (const __half2*)&p0;
#pragma unroll
        for (int i = 0; i < 4; i++) {
            float2 f0 = __half22float2(h0[i]);
            acc[2 * i]     += c0 * f0.x;
            acc[2 * i + 1] += c0 * f0.y;
        }
    }

    const float dd = g_dinv[g];
    float4 b0 = *(const float4*)(bias + t * 8);
    float4 b1 = *(const float4*)(bias + t * 8 + 4);
    float r[8];
    r[0] = fmaxf(dd * acc[0] + b0.x, 0.f);
    r[1] = fmaxf(dd * acc[1] + b0.y, 0.f);
    r[2] = fmaxf(dd * acc[2] + b0.z, 0.f);
    r[3] = fmaxf(dd * acc[3] + b0.w, 0.f);
    r[4] = fmaxf(dd * acc[4] + b1.x, 0.f);
    r[5] = fmaxf(dd * acc[5] + b1.y, 0.f);
    r[6] = fmaxf(dd * acc[6] + b1.z, 0.f);
    r[7] = fmaxf(dd * acc[7] + b1.w, 0.f);

    __half* dstp = ((mode == 0) ? g_A2 : g_H2h) + (size_t)g * DH + t * 8;
    uint4 outv;
    __half2* oh = (__half2*)&outv;
    oh[0] = __floats2half2_rn(r[0], r[1]);
    oh[1] = __floats2half2_rn(r[2], r[3]);
    oh[2] = __floats2half2_rn(r[4], r[5]);
    oh[3] = __floats2half2_rn(r[6], r[7]);
    *(uint4*)dstp = outv;
}

// ---------------- pooling + fc head: out[g] = mean_{batch==g}(h2) @ w_fc + b_fc --------------
__global__ __launch_bounds__(256) void k_pool(const int* __restrict__ batch,
                                              const float* __restrict__ wfc,
                                              const float* __restrict__ bfc,
                                              float* __restrict__ out) {
    const int g = blockIdx.x;
    __shared__ int s_lo, s_hi;
    __shared__ float red[256];
    if (threadIdx.x == 0) {
        int lo = 0, hi = NN;
        while (lo < hi) { int m = (lo + hi) >> 1; if (batch[m] < g) lo = m + 1; else hi = m; }
        s_lo = lo;
        hi = NN;
        while (lo < hi) { int m = (lo + hi) >> 1; if (batch[m] < g + 1) lo = m + 1; else hi = m; }
        s_hi = lo;
    }
    __syncthreads();
    const int lo = s_lo, hi = s_hi;
    const int f = threadIdx.x;
    float acc = 0.f;
    for (int r = lo; r < hi; r++) acc += __half2float(g_H2h[(size_t)r * DH + f]);
    float cnt = (float)((hi - lo) > 1 ? (hi - lo) : 1);
    red[f] = (acc / cnt) * wfc[f];
    __syncthreads();
    for (int off = 128; off > 0; off >>= 1) {
        if (f < off) red[f] += red[f + off];
        __syncthreads();
    }
    if (f == 0) out[g] = red[0] + bfc[0];
}

// ---------------- launch ----------------
extern "C" void kernel_launch(void* const* d_in, const int* in_sizes, int n_in,
                              void* d_out, int out_size) {
    const float* x    = (const float*)d_in[0];
    const int*   ei   = (const int*)d_in[1];   // [2, E]: row0 = src, row1 = dst
    const int*   bat  = (const int*)d_in[2];
    const float* W1   = (const float*)d_in[3];
    const float* b1   = (const float*)d_in[4];
    const float* W2   = (const float*)d_in[5];
    const float* b2   = (const float*)d_in[6];
    const float* wfc  = (const float*)d_in[7];
    const float* bfc  = (const float*)d_in[8];
    float* out = (float*)d_out;
    const int* src = ei;
    const int* dst = ei + EE;

    // one-time host-side resources (no device memory involved)
    static cudaStream_t s2 = nullptr;
    static cudaEvent_t evFork = nullptr, evJoin = nullptr;
    if (s2 == nullptr) {
        cudaStreamCreateWithFlags(&s2, cudaStreamNonBlocking);
        cudaEventCreateWithFlags(&evFork, cudaEventDisableTiming);
        cudaEventCreateWithFlags(&evJoin, cudaEventDisableTiming);
    }

    // ---- fork: CSR build (independent of the GEMM chain) on side stream ----
    cudaEventRecord(evFork, 0);
    cudaStreamWaitEvent(s2, evFork, 0);
    k_init<<<(NN + 255) / 256, 256, 0, s2>>>();
    k_count<<<(EE + 255) / 256, 256, 0, s2>>>(dst);
    k_scan<<<1, 1024, 0, s2>>>();
    k_fill<<<(EE + NN + 255) / 256, 256, 0, s2>>>(src, dst);
    cudaEventRecord(evJoin, s2);

    // ---- main stream: fp16 operands + GEMM layer 1 ----
    k_convx<<<(NN * DIN / 4 + 255) / 256, 256>>>(x);
    k_wprep<<<(DIN * DH + 255) / 256, 256>>>(W1, 0);
    k_wprep<<<(DH * DH + 255) / 256, 256>>>(W2, 1);

    dim3 gg((NN + BM - 1) / BM, DH / BN);   // 157 x 2

    k_gemm<<<gg, 256>>>(0, NN);

    // join: aggregation needs both the CSR and XW
    cudaStreamWaitEvent(0, evJoin, 0);
    k_agg<<<(NN + 7) / 8, 256>>>(b1, 0);

    // layer 2
    k_gemm<<<gg, 256>>>(1, NN);
    k_agg<<<(NN + 7) / 8, 256>>>(b2, 1);

    // pooling + head
    k_pool<<<GG, 256>>>(bat, wfc, bfc, out);
}

// round 16
// speedup vs baseline: 2.2420x; 1.0726x over previous
#include <cuda_runtime.h>
#include <cuda_fp16.h>
#include <cstdint>

// Problem constants (fixed by the dataset)
#define NN   20000
#define EE   320000
#define DIN  512
#define DH   256
#define GG   128

// ---------------- device scratch (static allocation only) ----------------
__device__ int       g_deg[NN];
__device__ int       g_cursor[NN];
__device__ int       g_rowptr[NN + 1];
__device__ float     g_dinv[NN];
__device__ int       g_csr[EE + NN];
__device__ __half    g_A1[(size_t)NN * DIN];   // fp16(x)
__device__ __half    g_A2[(size_t)NN * DH];    // fp16(h1) (written by agg1)
__device__ __half    g_W1h[(size_t)DIN * DH];  // fp16(W1), K-major
__device__ __half    g_W2h[(size_t)DH * DH];
__device__ __half    g_XWh[(size_t)NN * DH];   // GEMM output, fp16 (reused both layers)
__device__ float     g_ns[NN];                 // per-node scalar h2_n . w_fc

// ---------------- graph preprocessing ----------------
__global__ void k_init() {
    int i = blockIdx.x * blockDim.x + threadIdx.x;
    if (i < NN) { g_deg[i] = 1; g_cursor[i] = 0; }   // deg starts at 1 (self loop)
}

__global__ void k_count(const int* __restrict__ dst) {
    int e = blockIdx.x * blockDim.x + threadIdx.x;
    if (e < EE) atomicAdd(&g_deg[dst[e]], 1);
}

// single-block exclusive scan of g_deg -> g_rowptr, plus dinv = rsqrt(deg)
__global__ void k_scan() {
    __shared__ int partial[1024];
    const int tid = threadIdx.x;
    const int C = (NN + 1023) / 1024;   // 20
    int base = tid * C;
    int s = 0;
    for (int j = 0; j < C; j++) if (base + j < NN) s += g_deg[base + j];
    partial[tid] = s;
    __syncthreads();
    for (int off = 1; off < 1024; off <<= 1) {
        int v = (tid >= off) ? partial[tid - off] : 0;
        __syncthreads();
        partial[tid] += v;
        __syncthreads();
    }
    int run = partial[tid] - s;   // exclusive prefix for this chunk
    for (int j = 0; j < C; j++) {
        if (base + j < NN) {
            int d = g_deg[base + j];
            g_rowptr[base + j] = run;
            g_dinv[base + j] = rsqrtf((float)d);
            run += d;
        }
    }
    if (tid == 1023) g_rowptr[NN] = run;
}

__global__ void k_fill(const int* __restrict__ src, const int* __restrict__ dst) {
    int idx = blockIdx.x * blockDim.x + threadIdx.x;
    if (idx < EE) {
        int d = dst[idx];
        int pos = g_rowptr[d] + atomicAdd(&g_cursor[d], 1);
        g_csr[pos] = src[idx];
    } else if (idx < EE + NN) {
        int i = idx - EE;   // self loop
        int pos = g_rowptr[i] + atomicAdd(&g_cursor[i], 1);
        g_csr[pos] = i;
    }
}

// ---------------- fp16 conversions ----------------
__global__ void k_convx(const float* __restrict__ x) {
    int idx4 = blockIdx.x * blockDim.x + threadIdx.x;   // over NN*DIN/4
    if (idx4 >= NN * DIN / 4) return;
    float4 v = ((const float4*)x)[idx4];
    __half2 a = __halves2half2(__float2half(v.x), __float2half(v.y));
    __half2 b = __halves2half2(__float2half(v.z), __float2half(v.w));
    ((__half2*)g_A1)[idx4 * 2]     = a;
    ((__half2*)g_A1)[idx4 * 2 + 1] = b;
}

// both weight matrices rounded once to fp16 (K-major layouts preserved)
__global__ void k_wprep_both(const float* __restrict__ W1, const float* __restrict__ W2) {
    int idx = blockIdx.x * blockDim.x + threadIdx.x;
    if (idx < DIN * DH) {
        g_W1h[idx] = __float2half(W1[idx]);
    } else {
        int j = idx - DIN * DH;
        if (j < DH * DH) g_W2h[j] = __float2half(W2[j]);
    }
}

// ---------------- fp16 GEMM: C[M,256] = A[M,Kb] @ W[Kb,256], fp16 out ----------------
#define BM 128
#define BN 128
#define BK 32
#define AP (BK + 8)    // 40 half row stride (conflict-free ldmatrix)
#define BP (BN + 8)    // 136

#define MMA16816(d, a, b0_, b1_)                                                  \
    asm volatile("mma.sync.aligned.m16n8k16.row.col.f32.f16.f16.f32 "             \
                 "{%0,%1,%2,%3}, {%4,%5,%6,%7}, {%8,%9}, {%0,%1,%2,%3};"          \
                 : "+f"((d)[0]), "+f"((d)[1]), "+f"((d)[2]), "+f"((d)[3])          \
                 : "r"((a)[0]), "r"((a)[1]), "r"((a)[2]), "r"((a)[3]),             \
                   "r"(b0_), "r"(b1_))

__global__ __launch_bounds__(256, 2) void k_gemm(int layer, int M) {
    const __half* __restrict__ A = (layer == 0) ? g_A1 : g_A2;
    const __half* __restrict__ B = (layer == 0) ? g_W1h : g_W2h;
    __half* __restrict__ C = g_XWh;
    const int Kb = (layer == 0) ? DIN : DH;

    __shared__ __align__(16) __half As[2][BM][AP];
    __shared__ __align__(16) __half Bs[2][BK][BP];

    const int tid  = threadIdx.x;
    const int lane = tid & 31;
    const int wid  = tid >> 5;
    const int wm   = wid & 3;    // 4 warps along M, 32 rows each
    const int wn   = wid >> 2;   // 2 warps along N, 64 cols each
    const int bm   = blockIdx.x * BM;
    const int bn   = blockIdx.y * BN;

    float c[2][8][4];
#pragma unroll
    for (int mt = 0; mt < 2; mt++)
#pragma unroll
        for (int nt = 0; nt < 8; nt++)
#pragma unroll
            for (int r = 0; r < 4; r++) c[mt][nt][r] = 0.f;

    auto load_stage = [&](int buf, int kt) {
        const int k0 = kt * BK;
#pragma unroll
        for (int j = 0; j < 2; j++) {
            int ch = tid + j * 256;
            // A chunk: 512 x 16B
            int ar = ch >> 2, ac = (ch & 3) * 8;
            const __half* asrc = A + (size_t)(bm + ar) * Kb + k0 + ac;
            uint32_t adst = (uint32_t)__cvta_generic_to_shared(&As[buf][ar][ac]);
            int asz = (bm + ar < M) ? 16 : 0;
            asm volatile("cp.async.cg.shared.global [%0], [%1], 16, %2;\n"
                         :: "r"(adst), "l"(asrc), "r"(asz));
            // B chunk: 512 x 16B
            int br = ch >> 4, bc = (ch & 15) * 8;
            const __half* bsrc = B + (size_t)(k0 + br) * DH + bn + bc;
            uint32_t bdst = (uint32_t)__cvta_generic_to_shared(&Bs[buf][br][bc]);
            asm volatile("cp.async.cg.shared.global [%0], [%1], 16, %2;\n"
                         :: "r"(bdst), "l"(bsrc), "r"(16));
        }
        asm volatile("cp.async.commit_group;\n");
    };

    const int KT = Kb / BK;
    load_stage(0, 0);

    for (int kt = 0; kt < KT; ++kt) {
        asm volatile("cp.async.wait_group 0;\n");
        __syncthreads();
        if (kt + 1 < KT) load_stage((kt + 1) & 1, kt + 1);
        const int buf = kt & 1;

#pragma unroll
        for (int kk = 0; kk < BK; kk += 16) {
            uint32_t a[2][4];
#pragma unroll
            for (int mt = 0; mt < 2; mt++) {
                const __half* p =
                    &As[buf][wm * 32 + mt * 16 + (lane & 15)][kk + (lane >> 4) * 8];
                uint32_t sp = (uint32_t)__cvta_generic_to_shared(p);
                asm volatile("ldmatrix.sync.aligned.m8n8.x4.shared.b16 {%0,%1,%2,%3}, [%4];"
                             : "=r"(a[mt][0]), "=r"(a[mt][1]), "=r"(a[mt][2]), "=r"(a[mt][3])
                             : "r"(sp));
            }
#pragma unroll
            for (int ng = 0; ng < 4; ++ng) {
                uint32_t bb[4];
                const __half* p =
                    &Bs[buf][kk + (lane & 15)][wn * 64 + ng * 16 + (lane >> 4) * 8];
                uint32_t sp = (uint32_t)__cvta_generic_to_shared(p);
                asm volatile("ldmatrix.sync.aligned.m8n8.x4.trans.shared.b16 {%0,%1,%2,%3}, [%4];"
                             : "=r"(bb[0]), "=r"(bb[1]), "=r"(bb[2]), "=r"(bb[3])
                             : "r"(sp));
#pragma unroll
                for (int mt = 0; mt < 2; mt++) {
                    MMA16816(c[mt][2 * ng],     a[mt], bb[0], bb[1]);
                    MMA16816(c[mt][2 * ng + 1], a[mt], bb[2], bb[3]);
                }
            }
        }
    }

    // epilogue: fp16 stores
#pragma unroll
    for (int mt = 0; mt < 2; mt++) {
        int r0 = bm + wm * 32 + mt * 16 + (lane >> 2);
#pragma unroll
        for (int nt = 0; nt < 8; nt++) {
            int col = bn + wn * 64 + nt * 8 + (lane & 3) * 2;
            if (r0 < M)
                *(__half2*)&C[(size_t)r0 * DH + col] =
                    __floats2half2_rn(c[mt][nt][0], c[mt][nt][1]);
            if (r0 + 8 < M)
                *(__half2*)&C[(size_t)(r0 + 8) * DH + col] =
                    __floats2half2_rn(c[mt][nt][2], c[mt][nt][3]);
        }
    }
}

// ---------------- aggregation: r[d] = relu(dinv[d]*sum_{s in N(d)} dinv[s]*XW[s] + b) --------
// XW fp16 in, fp32 accumulate. mode 0 -> fp16 into g_A2 (feeds GEMM2).
// mode 1 -> per-node scalar r . w_fc into g_ns (feeds pooling; h2 never materialized).
__global__ __launch_bounds__(256) void k_agg(const float* __restrict__ bias,
                                             const float* __restrict__ wfc, int mode) {
    const int g = blockIdx.x * 8 + (threadIdx.x >> 5);   // dst node (one warp per node)
    const int t = threadIdx.x & 31;                      // owns features [8t, 8t+8)
    if (g >= NN) return;
    const int beg = g_rowptr[g], end = g_rowptr[g + 1];
    float acc[8];
#pragma unroll
    for (int i = 0; i < 8; i++) acc[i] = 0.f;
    const __half* __restrict__ xw = g_XWh;

    int e = beg;
    for (; e + 1 < end; e += 2) {
        int s0 = g_csr[e], s1 = g_csr[e + 1];
        float c0 = g_dinv[s0], c1 = g_dinv[s1];
        uint4 p0 = *(const uint4*)(xw + (size_t)s0 * DH + t * 8);
        uint4 p1 = *(const uint4*)(xw + (size_t)s1 * DH + t * 8);
        const __half2* h0 = (const __half2*)&p0;
        const __half2* h1 = (const __half2*)&p1;
#pragma unroll
        for (int i = 0; i < 4; i++) {
            float2 f0 = __half22float2(h0[i]);
            float2 f1 = __half22float2(h1[i]);
            acc[2 * i]     += c0 * f0.x + c1 * f1.x;
            acc[2 * i + 1] += c0 * f0.y + c1 * f1.y;
        }
    }
    if (e < end) {
        int s0 = g_csr[e];
        float c0 = g_dinv[s0];
        uint4 p0 = *(const uint4*)(xw + (size_t)s0 * DH + t * 8);
        const __half2* h0 = (const __half2*)&p0;
#pragma unroll
        for (int i = 0; i < 4; i++) {
            float2 f0 = __half22float2(h0[i]);
            acc[2 * i]     += c0 * f0.x;
            acc[2 * i + 1] += c0 * f0.y;
        }
    }

    const float dd = g_dinv[g];
    float4 b0 = *(const float4*)(bias + t * 8);
    float4 b1 = *(const float4*)(bias + t * 8 + 4);
    float r[8];
    r[0] = fmaxf(dd * acc[0] + b0.x, 0.f);
    r[1] = fmaxf(dd * acc[1] + b0.y, 0.f);
    r[2] = fmaxf(dd * acc[2] + b0.z, 0.f);
    r[3] = fmaxf(dd * acc[3] + b0.w, 0.f);
    r[4] = fmaxf(dd * acc[4] + b1.x, 0.f);
    r[5] = fmaxf(dd * acc[5] + b1.y, 0.f);
    r[6] = fmaxf(dd * acc[6] + b1.z, 0.f);
    r[7] = fmaxf(dd * acc[7] + b1.w, 0.f);

    if (mode == 0) {
        __half* dstp = g_A2 + (size_t)g * DH + t * 8;
        uint4 outv;
        __half2* oh = (__half2*)&outv;
        oh[0] = __floats2half2_rn(r[0], r[1]);
        oh[1] = __floats2half2_rn(r[2], r[3]);
        oh[2] = __floats2half2_rn(r[4], r[5]);
        oh[3] = __floats2half2_rn(r[6], r[7]);
        *(uint4*)dstp = outv;
    } else {
        // fused fc-head projection: s = h2[g] . w_fc  (h2 stays in registers)
        float4 w0 = *(const float4*)(wfc + t * 8);
        float4 w1 = *(const float4*)(wfc + t * 8 + 4);
        float s = r[0] * w0.x + r[1] * w0.y + r[2] * w0.z + r[3] * w0.w
                + r[4] * w1.x + r[5] * w1.y + r[6] * w1.z + r[7] * w1.w;
#pragma unroll
        for (int off = 16; off > 0; off >>= 1)
            s += __shfl_xor_sync(0xffffffffu, s, off);
        if (t == 0) g_ns[g] = s;
    }
}

// ---------------- pooling tail: out[g] = mean_{batch==g}(g_ns) + b_fc ----------------
__global__ __launch_bounds__(128) void k_pool2(const int* __restrict__ batch,
                                               const float* __restrict__ bfc,
                                               float* __restrict__ out) {
    const int g = blockIdx.x;
    __shared__ int s_lo, s_hi;
    __shared__ float red[128];
    if (threadIdx.x == 0) {
        int lo = 0, hi = NN;
        while (lo < hi) { int m = (lo + hi) >> 1; if (batch[m] < g) lo = m + 1; else hi = m; }
        s_lo = lo;
        hi = NN;
        while (lo < hi) { int m = (lo + hi) >> 1; if (batch[m] < g + 1) lo = m + 1; else hi = m; }
        s_hi = lo;
    }
    __syncthreads();
    const int lo = s_lo, hi = s_hi;
    const int f = threadIdx.x;
    float acc = 0.f;
    for (int r = lo + f; r < hi; r += 128) acc += g_ns[r];
    red[f] = acc;
    __syncthreads();
    for (int off = 64; off > 0; off >>= 1) {
        if (f < off) red[f] += red[f + off];
        __syncthreads();
    }
    if (f == 0) {
        float cnt = (float)((hi - lo) > 1 ? (hi - lo) : 1);
        out[g] = red[0] / cnt + bfc[0];
    }
}

// ---------------- launch ----------------
extern "C" void kernel_launch(void* const* d_in, const int* in_sizes, int n_in,
                              void* d_out, int out_size) {
    const float* x    = (const float*)d_in[0];
    const int*   ei   = (const int*)d_in[1];   // [2, E]: row0 = src, row1 = dst
    const int*   bat  = (const int*)d_in[2];
    const float* W1   = (const float*)d_in[3];
    const float* b1   = (const float*)d_in[4];
    const float* W2   = (const float*)d_in[5];
    const float* b2   = (const float*)d_in[6];
    const float* wfc  = (const float*)d_in[7];
    const float* bfc  = (const float*)d_in[8];
    float* out = (float*)d_out;
    const int* src = ei;
    const int* dst = ei + EE;

    // one-time host-side resources (no device memory involved)
    static cudaStream_t s2 = nullptr;
    static cudaEvent_t evFork = nullptr, evJoin = nullptr, evW = nullptr;
    if (s2 == nullptr) {
        cudaStreamCreateWithFlags(&s2, cudaStreamNonBlocking);
        cudaEventCreateWithFlags(&evFork, cudaEventDisableTiming);
        cudaEventCreateWithFlags(&evJoin, cudaEventDisableTiming);
        cudaEventCreateWithFlags(&evW, cudaEventDisableTiming);
    }

    // ---- fork: W conversion + CSR build on side stream ----
    cudaEventRecord(evFork, 0);
    cudaStreamWaitEvent(s2, evFork, 0);
    k_wprep_both<<<(DIN * DH + DH * DH + 255) / 256, 256, 0, s2>>>(W1, W2);
    cudaEventRecord(evW, s2);
    k_init<<<(NN + 255) / 256, 256, 0, s2>>>();
    k_count<<<(EE + 255) / 256, 256, 0, s2>>>(dst);
    k_scan<<<1, 1024, 0, s2>>>();
    k_fill<<<(EE + NN + 255) / 256, 256, 0, s2>>>(src, dst);
    cudaEventRecord(evJoin, s2);

    // ---- main stream: x conversion (overlaps with side stream) ----
    k_convx<<<(NN * DIN / 4 + 255) / 256, 256>>>(x);

    dim3 gg((NN + BM - 1) / BM, DH / BN);   // 157 x 2

    // layer 1 GEMM needs W1h from the side stream
    cudaStreamWaitEvent(0, evW, 0);
    k_gemm<<<gg, 256>>>(0, NN);

    // aggregation needs both the CSR and XW
    cudaStreamWaitEvent(0, evJoin, 0);
    k_agg<<<(NN + 7) / 8, 256>>>(b1, wfc, 0);

    // layer 2
    k_gemm<<<gg, 256>>>(1, NN);
    k_agg<<<(NN + 7) / 8, 256>>>(b2, wfc, 1);   // fused fc-head projection

    // pooling tail
    k_pool2<<<GG, 128>>>(bat, bfc, out);
}